// round 1
// baseline (speedup 1.0000x reference)
#include <cuda_runtime.h>
#include <cuda_bf16.h>
#include <cstdint>

// Problem constants
#define S_LEN 2048
#define D_MODEL 4096
#define N_HEADS 32
#define N_KV 8
#define HEAD_DIM 128
#define REP 4   // N_HEADS / N_KV

// Scratch (device globals; no allocations allowed)
__device__ float g_q[S_LEN * N_HEADS * HEAD_DIM];   // 2048 x 4096
__device__ float g_k[S_LEN * N_KV * HEAD_DIM];      // 2048 x 1024
__device__ float g_v[S_LEN * N_KV * HEAD_DIM];      // 2048 x 1024
__device__ float g_ao[S_LEN * N_HEADS * HEAD_DIM];  // 2048 x 4096

// ---------------------------------------------------------------------------
// Classic 128x128x8 fp32 SGEMM: C[M,N] = A[M,K] @ B[K,N], all row-major.
// 256 threads, 8x8 microtile per thread. Requires M%128==0, N%128==0, K%8==0.
// ---------------------------------------------------------------------------
__global__ void __launch_bounds__(256) sgemm128(const float* __restrict__ A,
                                                const float* __restrict__ B,
                                                float* __restrict__ C,
                                                int M, int N, int K) {
    __shared__ float As[8][128];
    __shared__ float Bs[8][132];  // pad to avoid store conflicts

    const int tid = threadIdx.x;
    const int brow = blockIdx.y * 128;
    const int bcol = blockIdx.x * 128;

    const int trow = (tid >> 4) << 3;  // (tid/16)*8
    const int tcol = (tid & 15) << 3;  // (tid%16)*8

    // A tile loader: each thread loads one float4. 128 rows x 8 cols.
    const int a_r = tid >> 1;          // 0..127
    const int a_c = (tid & 1) * 4;     // 0 or 4
    // B tile loader: 8 rows x 128 cols = 256 float4.
    const int b_r = tid >> 5;          // 0..7
    const int b_c = (tid & 31) << 2;   // 0..124

    const float* Aptr = A + (size_t)(brow + a_r) * K + a_c;
    const float* Bptr = B + (size_t)b_r * N + bcol + b_c;

    float acc[8][8];
#pragma unroll
    for (int i = 0; i < 8; i++)
#pragma unroll
        for (int j = 0; j < 8; j++) acc[i][j] = 0.f;

    for (int k0 = 0; k0 < K; k0 += 8) {
        float4 av = *(const float4*)(Aptr + k0);
        As[a_c + 0][a_r] = av.x;
        As[a_c + 1][a_r] = av.y;
        As[a_c + 2][a_r] = av.z;
        As[a_c + 3][a_r] = av.w;
        float4 bv = *(const float4*)(Bptr + (size_t)k0 * N);
        *(float4*)&Bs[b_r][b_c] = bv;
        __syncthreads();

#pragma unroll
        for (int kk = 0; kk < 8; kk++) {
            float ra[8], rb[8];
            *(float4*)&ra[0] = *(const float4*)&As[kk][trow];
            *(float4*)&ra[4] = *(const float4*)&As[kk][trow + 4];
            *(float4*)&rb[0] = *(const float4*)&Bs[kk][tcol];
            *(float4*)&rb[4] = *(const float4*)&Bs[kk][tcol + 4];
#pragma unroll
            for (int i = 0; i < 8; i++)
#pragma unroll
                for (int j = 0; j < 8; j++) acc[i][j] = fmaf(ra[i], rb[j], acc[i][j]);
        }
        __syncthreads();
    }

#pragma unroll
    for (int i = 0; i < 8; i++) {
        float* cp = C + (size_t)(brow + trow + i) * N + bcol + tcol;
        *(float4*)cp       = make_float4(acc[i][0], acc[i][1], acc[i][2], acc[i][3]);
        *(float4*)(cp + 4) = make_float4(acc[i][4], acc[i][5], acc[i][6], acc[i][7]);
    }
}

// ---------------------------------------------------------------------------
// RoPE (interleaved pairs, matches reference reshape (.., hd/2, 2)).
// t: [S, nheads, 128] row-major. cos/sin: [S, 64].
// ---------------------------------------------------------------------------
__global__ void rope_kernel(float* __restrict__ t,
                            const float* __restrict__ cosb,
                            const float* __restrict__ sinb,
                            int nheads) {
    int idx = blockIdx.x * blockDim.x + threadIdx.x;
    int total = S_LEN * nheads * (HEAD_DIM / 2);
    if (idx >= total) return;
    int p = idx & 63;                 // pair index 0..63
    int h = (idx >> 6) % nheads;
    int s = idx / (64 * nheads);
    float c = cosb[s * 64 + p];
    float sn = sinb[s * 64 + p];
    float* base = t + ((size_t)s * nheads + h) * HEAD_DIM + p * 2;
    float a = base[0], b = base[1];
    base[0] = a * c - b * sn;
    base[1] = a * sn + b * c;
}

// ---------------------------------------------------------------------------
// Flash-attention style fused causal attention (fp32, online softmax).
// Grid: (S/64 q-tiles, 32 heads). 256 threads.
// Each thread computes a 4x4 S-microtile and 4 rows x 8 dims of O.
// ---------------------------------------------------------------------------
#define BQ 64
#define BKV 64
#define QSTR (HEAD_DIM + 4)   // 132, conflict-free float4 row stride
#define PSTR (BKV + 1)        // 65

__global__ void __launch_bounds__(256) flash_kernel(const float* __restrict__ Q,
                                                    const float* __restrict__ K,
                                                    const float* __restrict__ V,
                                                    float* __restrict__ O) {
    extern __shared__ float sm[];
    float* Qs = sm;                       // BQ  x QSTR
    float* Ks = Qs + BQ * QSTR;           // BKV x QSTR
    float* Vs = Ks + BKV * QSTR;          // BKV x QSTR
    float* Ps = Vs + BKV * QSTR;          // BQ  x PSTR

    const int head = blockIdx.y;
    const int kvh = head >> 2;
    const int qt = gridDim.x - 1 - blockIdx.x;  // schedule big tiles first
    const int q0 = qt * BQ;
    const int tid = threadIdx.x;
    const int ti = tid >> 4;   // 0..15 row group
    const int tj = tid & 15;   // 0..15 col group
    const int r0 = ti * 4;
    const int c0 = tj * 4;

    const float scale = 0.08838834764831845f;  // 1/sqrt(128)

    // Load Q tile (prescaled)
    for (int idx = tid; idx < BQ * (HEAD_DIM / 4); idx += 256) {
        int r = idx >> 5;         // /32
        int d4 = (idx & 31) * 4;
        float4 v = *(const float4*)(Q + ((size_t)(q0 + r) * N_HEADS + head) * HEAD_DIM + d4);
        float* dst = &Qs[r * QSTR + d4];
        dst[0] = v.x * scale; dst[1] = v.y * scale;
        dst[2] = v.z * scale; dst[3] = v.w * scale;
    }

    float m_i[4], l_i[4], acc[4][8];
#pragma unroll
    for (int i = 0; i < 4; i++) {
        m_i[i] = -3.0e38f;
        l_i[i] = 0.f;
#pragma unroll
        for (int d = 0; d < 8; d++) acc[i][d] = 0.f;
    }

    const int ntiles = q0 / BKV + 1;
    for (int t = 0; t < ntiles; t++) {
        const int k0 = t * BKV;
        __syncthreads();  // protect Ks/Vs (and Qs on first iter) before overwrite

        // Load K,V tiles
        for (int idx = tid; idx < BKV * (HEAD_DIM / 4); idx += 256) {
            int j = idx >> 5;
            int d4 = (idx & 31) * 4;
            size_t goff = ((size_t)(k0 + j) * N_KV + kvh) * HEAD_DIM + d4;
            *(float4*)&Ks[j * QSTR + d4] = *(const float4*)(K + goff);
            *(float4*)&Vs[j * QSTR + d4] = *(const float4*)(V + goff);
        }
        __syncthreads();

        // S = Qs · Ks^T  (4x4 per thread)
        float s[4][4];
#pragma unroll
        for (int i = 0; i < 4; i++)
#pragma unroll
            for (int j = 0; j < 4; j++) s[i][j] = 0.f;

        for (int d4 = 0; d4 < HEAD_DIM; d4 += 4) {
            float4 qa[4], kb[4];
#pragma unroll
            for (int i = 0; i < 4; i++) qa[i] = *(const float4*)&Qs[(r0 + i) * QSTR + d4];
#pragma unroll
            for (int j = 0; j < 4; j++) kb[j] = *(const float4*)&Ks[(c0 + j) * QSTR + d4];
#pragma unroll
            for (int i = 0; i < 4; i++)
#pragma unroll
                for (int j = 0; j < 4; j++) {
                    s[i][j] = fmaf(qa[i].x, kb[j].x, s[i][j]);
                    s[i][j] = fmaf(qa[i].y, kb[j].y, s[i][j]);
                    s[i][j] = fmaf(qa[i].z, kb[j].z, s[i][j]);
                    s[i][j] = fmaf(qa[i].w, kb[j].w, s[i][j]);
                }
        }

        // Causal mask only on the diagonal tile
        if (t == ntiles - 1) {
#pragma unroll
            for (int i = 0; i < 4; i++)
#pragma unroll
                for (int j = 0; j < 4; j++)
                    if (k0 + c0 + j > q0 + r0 + i) s[i][j] = -3.0e38f;
        }

        // Row max (reduce over 16 lanes of row group; lanes l and l^{1,2,4,8})
        float mt[4];
#pragma unroll
        for (int i = 0; i < 4; i++) {
            float m = fmaxf(fmaxf(s[i][0], s[i][1]), fmaxf(s[i][2], s[i][3]));
#pragma unroll
            for (int off = 1; off < 16; off <<= 1)
                m = fmaxf(m, __shfl_xor_sync(0xffffffffu, m, off));
            mt[i] = m;
        }

        float alpha[4], rs[4];
#pragma unroll
        for (int i = 0; i < 4; i++) {
            float m_new = fmaxf(m_i[i], mt[i]);
            alpha[i] = __expf(m_i[i] - m_new);
            m_i[i] = m_new;
            float r = 0.f;
#pragma unroll
            for (int j = 0; j < 4; j++) {
                float p = __expf(s[i][j] - m_new);
                s[i][j] = p;
                r += p;
            }
#pragma unroll
            for (int off = 1; off < 16; off <<= 1)
                r += __shfl_xor_sync(0xffffffffu, r, off);
            rs[i] = r;
            l_i[i] = l_i[i] * alpha[i] + r;
        }

        // Rescale accumulators
#pragma unroll
        for (int i = 0; i < 4; i++)
#pragma unroll
            for (int d = 0; d < 8; d++) acc[i][d] *= alpha[i];

        // Stage P in shared
#pragma unroll
        for (int i = 0; i < 4; i++)
#pragma unroll
            for (int j = 0; j < 4; j++) Ps[(r0 + i) * PSTR + c0 + j] = s[i][j];
        __syncthreads();

        // O += P · V ; each thread owns rows r0..r0+3, dims tj*8..tj*8+7
        const int d0 = tj * 8;
#pragma unroll 4
        for (int j = 0; j < BKV; j++) {
            float4 v0 = *(const float4*)&Vs[j * QSTR + d0];
            float4 v1 = *(const float4*)&Vs[j * QSTR + d0 + 4];
#pragma unroll
            for (int i = 0; i < 4; i++) {
                float p = Ps[(r0 + i) * PSTR + j];
                acc[i][0] = fmaf(p, v0.x, acc[i][0]);
                acc[i][1] = fmaf(p, v0.y, acc[i][1]);
                acc[i][2] = fmaf(p, v0.z, acc[i][2]);
                acc[i][3] = fmaf(p, v0.w, acc[i][3]);
                acc[i][4] = fmaf(p, v1.x, acc[i][4]);
                acc[i][5] = fmaf(p, v1.y, acc[i][5]);
                acc[i][6] = fmaf(p, v1.z, acc[i][6]);
                acc[i][7] = fmaf(p, v1.w, acc[i][7]);
            }
        }
    }

    // Epilogue: normalize and write O[q, head*128 + d]
#pragma unroll
    for (int i = 0; i < 4; i++) {
        float inv = 1.0f / l_i[i];
        int row = q0 + r0 + i;
        float* op = O + ((size_t)row * N_HEADS + head) * HEAD_DIM + tj * 8;
        *(float4*)op       = make_float4(acc[i][0] * inv, acc[i][1] * inv,
                                         acc[i][2] * inv, acc[i][3] * inv);
        *(float4*)(op + 4) = make_float4(acc[i][4] * inv, acc[i][5] * inv,
                                         acc[i][6] * inv, acc[i][7] * inv);
    }
}

// ---------------------------------------------------------------------------
// Launch
// ---------------------------------------------------------------------------
extern "C" void kernel_launch(void* const* d_in, const int* in_sizes, int n_in,
                              void* d_out, int out_size) {
    const float* x  = (const float*)d_in[0];   // [2048, 4096]
    const float* fc = (const float*)d_in[1];   // [2048, 64]
    const float* fs = (const float*)d_in[2];   // [2048, 64]
    // d_in[3] = mask (unused; causal handled analytically)
    const float* wq = (const float*)d_in[4];   // [4096, 4096]
    const float* wk = (const float*)d_in[5];   // [4096, 1024]
    const float* wv = (const float*)d_in[6];   // [4096, 1024]
    const float* wo = (const float*)d_in[7];   // [4096, 4096]
    float* out = (float*)d_out;                // [2048, 4096]

    float *qp, *kp, *vp, *aop;
    cudaGetSymbolAddress((void**)&qp,  g_q);
    cudaGetSymbolAddress((void**)&kp,  g_k);
    cudaGetSymbolAddress((void**)&vp,  g_v);
    cudaGetSymbolAddress((void**)&aop, g_ao);

    // QKV projections
    sgemm128<<<dim3(D_MODEL / 128, S_LEN / 128), 256>>>(x, wq, qp, S_LEN, D_MODEL, D_MODEL);
    sgemm128<<<dim3((N_KV * HEAD_DIM) / 128, S_LEN / 128), 256>>>(x, wk, kp, S_LEN, N_KV * HEAD_DIM, D_MODEL);
    sgemm128<<<dim3((N_KV * HEAD_DIM) / 128, S_LEN / 128), 256>>>(x, wv, vp, S_LEN, N_KV * HEAD_DIM, D_MODEL);

    // RoPE on Q and K
    {
        int totq = S_LEN * N_HEADS * (HEAD_DIM / 2);
        int totk = S_LEN * N_KV * (HEAD_DIM / 2);
        rope_kernel<<<(totq + 255) / 256, 256>>>(qp, fc, fs, N_HEADS);
        rope_kernel<<<(totk + 255) / 256, 256>>>(kp, fc, fs, N_KV);
    }

    // Fused causal attention
    {
        size_t smem = (size_t)(BQ * QSTR * 3 + BQ * PSTR) * sizeof(float);  // ~115 KB
        cudaFuncSetAttribute(flash_kernel, cudaFuncAttributeMaxDynamicSharedMemorySize, (int)smem);
        flash_kernel<<<dim3(S_LEN / BQ, N_HEADS), 256, smem>>>(qp, kp, vp, aop);
    }

    // Output projection
    sgemm128<<<dim3(D_MODEL / 128, S_LEN / 128), 256>>>(aop, wo, out, S_LEN, D_MODEL, D_MODEL);
}

// round 3
// speedup vs baseline: 1.7796x; 1.7796x over previous
#include <cuda_runtime.h>
#include <cuda_fp16.h>
#include <cuda_bf16.h>
#include <cstdint>

// Problem constants
#define S_LEN 2048
#define D_MODEL 4096
#define N_HEADS 32
#define N_KV 8
#define HEAD_DIM 128
#define KVDIM (N_KV * HEAD_DIM)   // 1024

#define WSCALE 64.0f
#define INV_WSCALE (1.0f / 64.0f)

// ---------------------------------------------------------------------------
// Scratch (device globals; no allocations allowed)
// ---------------------------------------------------------------------------
__device__ __align__(128) float g_q[S_LEN * D_MODEL];
__device__ __align__(128) float g_k[S_LEN * KVDIM];
__device__ __align__(128) float g_v[S_LEN * KVDIM];
__device__ __align__(128) float g_ao[S_LEN * D_MODEL];

__device__ __align__(128) __half g_xh[S_LEN * D_MODEL];
__device__ __align__(128) __half g_xl[S_LEN * D_MODEL];
__device__ __align__(128) __half g_aoh[S_LEN * D_MODEL];
__device__ __align__(128) __half g_aol[S_LEN * D_MODEL];
__device__ __align__(128) __half g_wqh[D_MODEL * D_MODEL];  // [N,K], x64
__device__ __align__(128) __half g_wql[D_MODEL * D_MODEL];
__device__ __align__(128) __half g_wkh[KVDIM * D_MODEL];
__device__ __align__(128) __half g_wkl[KVDIM * D_MODEL];
__device__ __align__(128) __half g_wvh[KVDIM * D_MODEL];
__device__ __align__(128) __half g_wvl[KVDIM * D_MODEL];
__device__ __align__(128) __half g_woh[D_MODEL * D_MODEL];
__device__ __align__(128) __half g_wol[D_MODEL * D_MODEL];

// ---------------------------------------------------------------------------
// HMMA GEMM with fp16 hi/lo split: C = cscale * (Ah+Al)[M,K] @ (Bh+Bl)[N,K]^T
// (drops Al*Bl). 128x128 tile, K-chunk 64, cp.async double buffer.
// ---------------------------------------------------------------------------
#define G_ROWB 144          // 72 halves per row (64 + 8 pad), conflict-free
#define G_TILEB (128 * G_ROWB)          // 18432
#define G_STAGE (4 * G_TILEB)           // 73728
#define G_SMEM (2 * G_STAGE)            // 147456

__device__ __forceinline__ uint32_t smem_u32(const void* p) {
    uint32_t a;
    asm("{ .reg .u64 t; cvta.to.shared.u64 t, %1; cvt.u32.u64 %0, t; }"
        : "=r"(a) : "l"(p));
    return a;
}

#define LDSM4(r0, r1, r2, r3, addr)                                           \
    asm volatile("ldmatrix.sync.aligned.m8n8.x4.shared.b16 {%0,%1,%2,%3}, [%4];" \
                 : "=r"(r0), "=r"(r1), "=r"(r2), "=r"(r3) : "r"(addr))

#define MMA16816(d, a, b)                                                     \
    asm volatile(                                                             \
        "mma.sync.aligned.m16n8k16.row.col.f32.f16.f16.f32 "                  \
        "{%0,%1,%2,%3}, {%4,%5,%6,%7}, {%8,%9}, {%0,%1,%2,%3};"               \
        : "+f"((d)[0]), "+f"((d)[1]), "+f"((d)[2]), "+f"((d)[3])              \
        : "r"((a)[0]), "r"((a)[1]), "r"((a)[2]), "r"((a)[3]),                 \
          "r"((b)[0]), "r"((b)[1]))

__global__ void __launch_bounds__(256, 1)
gemm_hmma_split(const __half* __restrict__ Ah, const __half* __restrict__ Al,
                const __half* __restrict__ Bh, const __half* __restrict__ Bl,
                float* __restrict__ C, int M, int N, int K, float cscale) {
    extern __shared__ char smem[];
    const uint32_t sb = smem_u32(smem);
    const int tid = threadIdx.x;
    const int lane = tid & 31;
    const int wid = tid >> 5;
    const int wm = wid & 3;        // 4 warps along M (32 rows each)
    const int wn = wid >> 2;       // 2 warps along N (64 cols each)
    const int m0 = blockIdx.y * 128;
    const int n0 = blockIdx.x * 128;

    // Loader precompute: 4 cp.async per tile per thread
    uint32_t s_off[4];
    size_t g_off[4];
#pragma unroll
    for (int it = 0; it < 4; it++) {
        int idx = it * 256 + tid;
        int r = idx >> 3;
        int c = idx & 7;
        s_off[it] = (uint32_t)(r * G_ROWB + c * 16);
        g_off[it] = (size_t)r * K + c * 8;
    }
    const __half* src[4] = {Ah + (size_t)m0 * K, Al + (size_t)m0 * K,
                            Bh + (size_t)n0 * K, Bl + (size_t)n0 * K};

    auto issue = [&](int i) {
        const uint32_t sbase = sb + (i & 1) * G_STAGE;
        const int k0 = i << 6;
#pragma unroll
        for (int t4 = 0; t4 < 4; t4++) {
            const __half* g = src[t4] + k0;
            const uint32_t st = sbase + t4 * G_TILEB;
#pragma unroll
            for (int it = 0; it < 4; it++) {
                asm volatile("cp.async.cg.shared.global [%0], [%1], 16;"
                             :: "r"(st + s_off[it]), "l"(g + g_off[it]) : "memory");
            }
        }
        asm volatile("cp.async.commit_group;" ::: "memory");
    };

    // ldmatrix per-lane address offsets (within stage)
    uint32_t aoff[2], boff[4];
#pragma unroll
    for (int mt = 0; mt < 2; mt++) {
        int row = wm * 32 + mt * 16 + (lane & 15);
        aoff[mt] = (uint32_t)(row * G_ROWB + (lane >> 4) * 16);
    }
#pragma unroll
    for (int ng = 0; ng < 4; ng++) {
        int row = wn * 64 + ng * 16 + (lane & 15);
        boff[ng] = (uint32_t)(2 * G_TILEB + row * G_ROWB + (lane >> 4) * 16);
    }

    float acc[2][8][4];
#pragma unroll
    for (int mt = 0; mt < 2; mt++)
#pragma unroll
        for (int n = 0; n < 8; n++)
#pragma unroll
            for (int e = 0; e < 4; e++) acc[mt][n][e] = 0.f;

    const int niter = K >> 6;
    issue(0);

    for (int i = 0; i < niter; i++) {
        if (i + 1 < niter) {
            issue(i + 1);
            asm volatile("cp.async.wait_group 1;" ::: "memory");
        } else {
            asm volatile("cp.async.wait_group 0;" ::: "memory");
        }
        __syncthreads();

        const uint32_t st = sb + (i & 1) * G_STAGE;
#pragma unroll
        for (int ks = 0; ks < 4; ks++) {
            const uint32_t kadd = ks * 32;
            uint32_t ah[2][4], al[2][4], bh[8][2], bl[8][2];
#pragma unroll
            for (int mt = 0; mt < 2; mt++) {
                LDSM4(ah[mt][0], ah[mt][1], ah[mt][2], ah[mt][3],
                      st + aoff[mt] + kadd);
                LDSM4(al[mt][0], al[mt][1], al[mt][2], al[mt][3],
                      st + G_TILEB + aoff[mt] + kadd);
            }
#pragma unroll
            for (int ng = 0; ng < 4; ng++) {
                uint32_t r0, r1, r2, r3;
                LDSM4(r0, r1, r2, r3, st + boff[ng] + kadd);
                bh[ng * 2][0] = r0; bh[ng * 2][1] = r2;
                bh[ng * 2 + 1][0] = r1; bh[ng * 2 + 1][1] = r3;
                LDSM4(r0, r1, r2, r3, st + G_TILEB + boff[ng] + kadd);
                bl[ng * 2][0] = r0; bl[ng * 2][1] = r2;
                bl[ng * 2 + 1][0] = r1; bl[ng * 2 + 1][1] = r3;
            }
#pragma unroll
            for (int mt = 0; mt < 2; mt++)
#pragma unroll
                for (int n = 0; n < 8; n++) {
                    MMA16816(acc[mt][n], ah[mt], bh[n]);
                    MMA16816(acc[mt][n], al[mt], bh[n]);
                    MMA16816(acc[mt][n], ah[mt], bl[n]);
                }
        }
        __syncthreads();
    }

    // Epilogue
    const int row_b = m0 + wm * 32 + (lane >> 2);
    const int col_b = n0 + wn * 64 + (lane & 3) * 2;
#pragma unroll
    for (int mt = 0; mt < 2; mt++)
#pragma unroll
        for (int n = 0; n < 8; n++) {
            float* c0 = C + (size_t)(row_b + mt * 16) * N + col_b + n * 8;
            float* c1 = c0 + 8 * N;
            c0[0] = acc[mt][n][0] * cscale;
            c0[1] = acc[mt][n][1] * cscale;
            c1[0] = acc[mt][n][2] * cscale;
            c1[1] = acc[mt][n][3] * cscale;
        }
}

// ---------------------------------------------------------------------------
// fp32 -> fp16 hi/lo split (elementwise), optional pre-scale
// ---------------------------------------------------------------------------
__global__ void split_kernel(const float* __restrict__ in,
                             __half* __restrict__ hi, __half* __restrict__ lo,
                             int n) {
    int i = blockIdx.x * blockDim.x + threadIdx.x;
    if (i >= n) return;
    float v = in[i];
    __half h = __float2half_rn(v);
    hi[i] = h;
    lo[i] = __float2half_rn(v - __half2float(h));
}

// W [K,N] row-major -> hi/lo [N,K] (transpose + split + x64 scale)
__global__ void __launch_bounds__(256) transpose_split(
    const float* __restrict__ W, __half* __restrict__ hi,
    __half* __restrict__ lo, int K, int N) {
    __shared__ float t[32][33];
    const int n0 = blockIdx.x * 32;
    const int k0 = blockIdx.y * 32;
    const int tx = threadIdx.x;
#pragma unroll
    for (int j = threadIdx.y; j < 32; j += 8)
        t[j][tx] = W[(size_t)(k0 + j) * N + n0 + tx];
    __syncthreads();
#pragma unroll
    for (int j = threadIdx.y; j < 32; j += 8) {
        float v = t[tx][j] * WSCALE;   // = W[k0+tx][n0+j] * 64
        __half h = __float2half_rn(v);
        size_t o = (size_t)(n0 + j) * K + k0 + tx;
        hi[o] = h;
        lo[o] = __float2half_rn(v - __half2float(h));
    }
}

// ---------------------------------------------------------------------------
// RoPE (interleaved pairs). t: [S, nheads, 128]; cos/sin: [S, 64].
// ---------------------------------------------------------------------------
__global__ void rope_kernel(float* __restrict__ t,
                            const float* __restrict__ cosb,
                            const float* __restrict__ sinb, int nheads) {
    int idx = blockIdx.x * blockDim.x + threadIdx.x;
    int total = S_LEN * nheads * (HEAD_DIM / 2);
    if (idx >= total) return;
    int p = idx & 63;
    int h = (idx >> 6) % nheads;
    int s = idx / (64 * nheads);
    float c = cosb[s * 64 + p];
    float sn = sinb[s * 64 + p];
    float* base = t + ((size_t)s * nheads + h) * HEAD_DIM + p * 2;
    float a = base[0], b = base[1];
    base[0] = a * c - b * sn;
    base[1] = a * sn + b * c;
}

// ---------------------------------------------------------------------------
// Flash-attention style fused causal attention (fp32, online softmax).
// ---------------------------------------------------------------------------
#define BQ 64
#define BKV 64
#define QSTR (HEAD_DIM + 4)
#define PSTR (BKV + 1)

__global__ void __launch_bounds__(256) flash_kernel(const float* __restrict__ Q,
                                                    const float* __restrict__ K,
                                                    const float* __restrict__ V,
                                                    float* __restrict__ O) {
    extern __shared__ float sm[];
    float* Qs = sm;
    float* Ks = Qs + BQ * QSTR;
    float* Vs = Ks + BKV * QSTR;
    float* Ps = Vs + BKV * QSTR;

    const int head = blockIdx.y;
    const int kvh = head >> 2;
    const int qt = gridDim.x - 1 - blockIdx.x;
    const int q0 = qt * BQ;
    const int tid = threadIdx.x;
    const int ti = tid >> 4;
    const int tj = tid & 15;
    const int r0 = ti * 4;
    const int c0 = tj * 4;

    const float scale = 0.08838834764831845f;

    for (int idx = tid; idx < BQ * (HEAD_DIM / 4); idx += 256) {
        int r = idx >> 5;
        int d4 = (idx & 31) * 4;
        float4 v = *(const float4*)(Q + ((size_t)(q0 + r) * N_HEADS + head) * HEAD_DIM + d4);
        float* dst = &Qs[r * QSTR + d4];
        dst[0] = v.x * scale; dst[1] = v.y * scale;
        dst[2] = v.z * scale; dst[3] = v.w * scale;
    }

    float m_i[4], l_i[4], acc[4][8];
#pragma unroll
    for (int i = 0; i < 4; i++) {
        m_i[i] = -3.0e38f;
        l_i[i] = 0.f;
#pragma unroll
        for (int d = 0; d < 8; d++) acc[i][d] = 0.f;
    }

    const int ntiles = q0 / BKV + 1;
    for (int t = 0; t < ntiles; t++) {
        const int k0 = t * BKV;
        __syncthreads();
        for (int idx = tid; idx < BKV * (HEAD_DIM / 4); idx += 256) {
            int j = idx >> 5;
            int d4 = (idx & 31) * 4;
            size_t goff = ((size_t)(k0 + j) * N_KV + kvh) * HEAD_DIM + d4;
            *(float4*)&Ks[j * QSTR + d4] = *(const float4*)(K + goff);
            *(float4*)&Vs[j * QSTR + d4] = *(const float4*)(V + goff);
        }
        __syncthreads();

        float s[4][4];
#pragma unroll
        for (int i = 0; i < 4; i++)
#pragma unroll
            for (int j = 0; j < 4; j++) s[i][j] = 0.f;

        for (int d4 = 0; d4 < HEAD_DIM; d4 += 4) {
            float4 qa[4], kb[4];
#pragma unroll
            for (int i = 0; i < 4; i++) qa[i] = *(const float4*)&Qs[(r0 + i) * QSTR + d4];
#pragma unroll
            for (int j = 0; j < 4; j++) kb[j] = *(const float4*)&Ks[(c0 + j) * QSTR + d4];
#pragma unroll
            for (int i = 0; i < 4; i++)
#pragma unroll
                for (int j = 0; j < 4; j++) {
                    s[i][j] = fmaf(qa[i].x, kb[j].x, s[i][j]);
                    s[i][j] = fmaf(qa[i].y, kb[j].y, s[i][j]);
                    s[i][j] = fmaf(qa[i].z, kb[j].z, s[i][j]);
                    s[i][j] = fmaf(qa[i].w, kb[j].w, s[i][j]);
                }
        }

        if (t == ntiles - 1) {
#pragma unroll
            for (int i = 0; i < 4; i++)
#pragma unroll
                for (int j = 0; j < 4; j++)
                    if (k0 + c0 + j > q0 + r0 + i) s[i][j] = -3.0e38f;
        }

        float mt[4];
#pragma unroll
        for (int i = 0; i < 4; i++) {
            float m = fmaxf(fmaxf(s[i][0], s[i][1]), fmaxf(s[i][2], s[i][3]));
#pragma unroll
            for (int off = 1; off < 16; off <<= 1)
                m = fmaxf(m, __shfl_xor_sync(0xffffffffu, m, off));
            mt[i] = m;
        }

        float alpha[4];
#pragma unroll
        for (int i = 0; i < 4; i++) {
            float m_new = fmaxf(m_i[i], mt[i]);
            alpha[i] = __expf(m_i[i] - m_new);
            m_i[i] = m_new;
            float r = 0.f;
#pragma unroll
            for (int j = 0; j < 4; j++) {
                float p = __expf(s[i][j] - m_new);
                s[i][j] = p;
                r += p;
            }
#pragma unroll
            for (int off = 1; off < 16; off <<= 1)
                r += __shfl_xor_sync(0xffffffffu, r, off);
            l_i[i] = l_i[i] * alpha[i] + r;
        }

#pragma unroll
        for (int i = 0; i < 4; i++)
#pragma unroll
            for (int d = 0; d < 8; d++) acc[i][d] *= alpha[i];

#pragma unroll
        for (int i = 0; i < 4; i++)
#pragma unroll
            for (int j = 0; j < 4; j++) Ps[(r0 + i) * PSTR + c0 + j] = s[i][j];
        __syncthreads();

        const int d0 = tj * 8;
#pragma unroll 4
        for (int j = 0; j < BKV; j++) {
            float4 v0 = *(const float4*)&Vs[j * QSTR + d0];
            float4 v1 = *(const float4*)&Vs[j * QSTR + d0 + 4];
#pragma unroll
            for (int i = 0; i < 4; i++) {
                float p = Ps[(r0 + i) * PSTR + j];
                acc[i][0] = fmaf(p, v0.x, acc[i][0]);
                acc[i][1] = fmaf(p, v0.y, acc[i][1]);
                acc[i][2] = fmaf(p, v0.z, acc[i][2]);
                acc[i][3] = fmaf(p, v0.w, acc[i][3]);
                acc[i][4] = fmaf(p, v1.x, acc[i][4]);
                acc[i][5] = fmaf(p, v1.y, acc[i][5]);
                acc[i][6] = fmaf(p, v1.z, acc[i][6]);
                acc[i][7] = fmaf(p, v1.w, acc[i][7]);
            }
        }
    }

#pragma unroll
    for (int i = 0; i < 4; i++) {
        float inv = 1.0f / l_i[i];
        int row = q0 + r0 + i;
        float* op = O + ((size_t)row * N_HEADS + head) * HEAD_DIM + tj * 8;
        *(float4*)op       = make_float4(acc[i][0] * inv, acc[i][1] * inv,
                                         acc[i][2] * inv, acc[i][3] * inv);
        *(float4*)(op + 4) = make_float4(acc[i][4] * inv, acc[i][5] * inv,
                                         acc[i][6] * inv, acc[i][7] * inv);
    }
}

// ---------------------------------------------------------------------------
// Launch
// ---------------------------------------------------------------------------
extern "C" void kernel_launch(void* const* d_in, const int* in_sizes, int n_in,
                              void* d_out, int out_size) {
    const float* x  = (const float*)d_in[0];
    const float* fc = (const float*)d_in[1];
    const float* fs = (const float*)d_in[2];
    const float* wq = (const float*)d_in[4];
    const float* wk = (const float*)d_in[5];
    const float* wv = (const float*)d_in[6];
    const float* wo = (const float*)d_in[7];
    float* out = (float*)d_out;

    float *qp, *kp, *vp, *aop;
    __half *xh, *xl, *aoh, *aol, *wqh, *wql, *wkh, *wkl, *wvh, *wvl, *woh, *wol;
    cudaGetSymbolAddress((void**)&qp,  g_q);
    cudaGetSymbolAddress((void**)&kp,  g_k);
    cudaGetSymbolAddress((void**)&vp,  g_v);
    cudaGetSymbolAddress((void**)&aop, g_ao);
    cudaGetSymbolAddress((void**)&xh,  g_xh);
    cudaGetSymbolAddress((void**)&xl,  g_xl);
    cudaGetSymbolAddress((void**)&aoh, g_aoh);
    cudaGetSymbolAddress((void**)&aol, g_aol);
    cudaGetSymbolAddress((void**)&wqh, g_wqh);
    cudaGetSymbolAddress((void**)&wql, g_wql);
    cudaGetSymbolAddress((void**)&wkh, g_wkh);
    cudaGetSymbolAddress((void**)&wkl, g_wkl);
    cudaGetSymbolAddress((void**)&wvh, g_wvh);
    cudaGetSymbolAddress((void**)&wvl, g_wvl);
    cudaGetSymbolAddress((void**)&woh, g_woh);
    cudaGetSymbolAddress((void**)&wol, g_wol);

    cudaFuncSetAttribute(gemm_hmma_split,
                         cudaFuncAttributeMaxDynamicSharedMemorySize, G_SMEM);

    // Convert inputs / weights (weights transposed to [N,K], scaled x64)
    split_kernel<<<(S_LEN * D_MODEL + 255) / 256, 256>>>(x, xh, xl, S_LEN * D_MODEL);
    transpose_split<<<dim3(D_MODEL / 32, D_MODEL / 32), dim3(32, 8)>>>(wq, wqh, wql, D_MODEL, D_MODEL);
    transpose_split<<<dim3(KVDIM / 32,  D_MODEL / 32), dim3(32, 8)>>>(wk, wkh, wkl, D_MODEL, KVDIM);
    transpose_split<<<dim3(KVDIM / 32,  D_MODEL / 32), dim3(32, 8)>>>(wv, wvh, wvl, D_MODEL, KVDIM);
    transpose_split<<<dim3(D_MODEL / 32, D_MODEL / 32), dim3(32, 8)>>>(wo, woh, wol, D_MODEL, D_MODEL);

    // QKV projections on tensor cores (HMMA)
    gemm_hmma_split<<<dim3(D_MODEL / 128, S_LEN / 128), 256, G_SMEM>>>(
        xh, xl, wqh, wql, qp, S_LEN, D_MODEL, D_MODEL, INV_WSCALE);
    gemm_hmma_split<<<dim3(KVDIM / 128, S_LEN / 128), 256, G_SMEM>>>(
        xh, xl, wkh, wkl, kp, S_LEN, KVDIM, D_MODEL, INV_WSCALE);
    gemm_hmma_split<<<dim3(KVDIM / 128, S_LEN / 128), 256, G_SMEM>>>(
        xh, xl, wvh, wvl, vp, S_LEN, KVDIM, D_MODEL, INV_WSCALE);

    // RoPE
    rope_kernel<<<(S_LEN * N_HEADS * 64 + 255) / 256, 256>>>(qp, fc, fs, N_HEADS);
    rope_kernel<<<(S_LEN * N_KV * 64 + 255) / 256, 256>>>(kp, fc, fs, N_KV);

    // Fused causal attention (fp32)
    {
        size_t smem = (size_t)(BQ * QSTR * 3 + BQ * PSTR) * sizeof(float);
        cudaFuncSetAttribute(flash_kernel, cudaFuncAttributeMaxDynamicSharedMemorySize, (int)smem);
        flash_kernel<<<dim3(S_LEN / BQ, N_HEADS), 256, smem>>>(qp, kp, vp, aop);
    }

    // Output projection
    split_kernel<<<(S_LEN * D_MODEL + 255) / 256, 256>>>(aop, aoh, aol, S_LEN * D_MODEL);
    gemm_hmma_split<<<dim3(D_MODEL / 128, S_LEN / 128), 256, G_SMEM>>>(
        aoh, aol, woh, wol, out, S_LEN, D_MODEL, D_MODEL, INV_WSCALE);
}

// round 4
// speedup vs baseline: 3.1059x; 1.7453x over previous
#include <cuda_runtime.h>
#include <cuda_fp16.h>
#include <cstdint>

// Problem constants
#define S_LEN 2048
#define D_MODEL 4096
#define N_HEADS 32
#define N_KV 8
#define HEAD_DIM 128
#define KVDIM (N_KV * HEAD_DIM)   // 1024

#define WSCALE 64.0f
#define INV_WSCALE (1.0f / 64.0f)
#define QK_SCALE 0.08838834764831845f  // 1/sqrt(128)

// ---------------------------------------------------------------------------
// Scratch (device globals)
// ---------------------------------------------------------------------------
__device__ __align__(128) __half g_xh[S_LEN * D_MODEL];
__device__ __align__(128) __half g_xl[S_LEN * D_MODEL];
__device__ __align__(128) __half g_qh[S_LEN * D_MODEL];
__device__ __align__(128) __half g_ql[S_LEN * D_MODEL];
__device__ __align__(128) __half g_kh[S_LEN * KVDIM];
__device__ __align__(128) __half g_kl[S_LEN * KVDIM];
__device__ __align__(128) __half g_vh[S_LEN * KVDIM];
__device__ __align__(128) __half g_vl[S_LEN * KVDIM];
__device__ __align__(128) __half g_aoh[S_LEN * D_MODEL];
__device__ __align__(128) __half g_aol[S_LEN * D_MODEL];
__device__ __align__(128) __half g_wqh[D_MODEL * D_MODEL];  // [N,K], x64
__device__ __align__(128) __half g_wql[D_MODEL * D_MODEL];
__device__ __align__(128) __half g_wkh[KVDIM * D_MODEL];
__device__ __align__(128) __half g_wkl[KVDIM * D_MODEL];
__device__ __align__(128) __half g_wvh[KVDIM * D_MODEL];
__device__ __align__(128) __half g_wvl[KVDIM * D_MODEL];
__device__ __align__(128) __half g_woh[D_MODEL * D_MODEL];
__device__ __align__(128) __half g_wol[D_MODEL * D_MODEL];

// ---------------------------------------------------------------------------
// Common helpers
// ---------------------------------------------------------------------------
__device__ __forceinline__ uint32_t smem_u32(const void* p) {
    uint32_t a;
    asm("{ .reg .u64 t; cvta.to.shared.u64 t, %1; cvt.u32.u64 %0, t; }"
        : "=r"(a) : "l"(p));
    return a;
}

__device__ __forceinline__ uint32_t pack_h2f(float a, float b) {
    __half2 h = __floats2half2_rn(a, b);
    return *reinterpret_cast<uint32_t*>(&h);
}
__device__ __forceinline__ uint32_t pack_resid(uint32_t h, float a, float b) {
    __half2 hh = *reinterpret_cast<__half2*>(&h);
    float2 f = __half22float2(hh);
    return pack_h2f(a - f.x, b - f.y);
}

#define LDSM4(r0, r1, r2, r3, addr)                                           \
    asm volatile("ldmatrix.sync.aligned.m8n8.x4.shared.b16 {%0,%1,%2,%3}, [%4];" \
                 : "=r"(r0), "=r"(r1), "=r"(r2), "=r"(r3) : "r"(addr))

#define LDSM4T(r0, r1, r2, r3, addr)                                          \
    asm volatile("ldmatrix.sync.aligned.m8n8.x4.trans.shared.b16 {%0,%1,%2,%3}, [%4];" \
                 : "=r"(r0), "=r"(r1), "=r"(r2), "=r"(r3) : "r"(addr))

#define MMA16816(d, a, b)                                                     \
    asm volatile(                                                             \
        "mma.sync.aligned.m16n8k16.row.col.f32.f16.f16.f32 "                  \
        "{%0,%1,%2,%3}, {%4,%5,%6,%7}, {%8,%9}, {%0,%1,%2,%3};"               \
        : "+f"((d)[0]), "+f"((d)[1]), "+f"((d)[2]), "+f"((d)[3])              \
        : "r"((a)[0]), "r"((a)[1]), "r"((a)[2]), "r"((a)[3]),                 \
          "r"((b)[0]), "r"((b)[1]))

#define CP16(s, g)                                                            \
    asm volatile("cp.async.cg.shared.global [%0], [%1], 16;"                  \
                 :: "r"(s), "l"(g) : "memory")

// ---------------------------------------------------------------------------
// HMMA GEMM with fp16 hi/lo split. MODE 0: fp32 out. MODE 1: rope+split out.
// MODE 2: split out.
// ---------------------------------------------------------------------------
#define G_ROWB 144
#define G_TILEB (128 * G_ROWB)
#define G_STAGE (4 * G_TILEB)
#define G_SMEM (2 * G_STAGE)

template <int MODE>
__global__ void __launch_bounds__(256, 1)
gemm_hmma_split(const __half* __restrict__ Ah, const __half* __restrict__ Al,
                const __half* __restrict__ Bh, const __half* __restrict__ Bl,
                float* __restrict__ Cf, __half* __restrict__ Ch,
                __half* __restrict__ Cl, const float* __restrict__ fc,
                const float* __restrict__ fs, int M, int N, int K,
                float cscale, float oscale) {
    extern __shared__ char smem[];
    const uint32_t sb = smem_u32(smem);
    const int tid = threadIdx.x;
    const int lane = tid & 31;
    const int wid = tid >> 5;
    const int wm = wid & 3;
    const int wn = wid >> 2;
    const int m0 = blockIdx.y * 128;
    const int n0 = blockIdx.x * 128;

    uint32_t s_off[4];
    size_t g_off[4];
#pragma unroll
    for (int it = 0; it < 4; it++) {
        int idx = it * 256 + tid;
        int r = idx >> 3;
        int c = idx & 7;
        s_off[it] = (uint32_t)(r * G_ROWB + c * 16);
        g_off[it] = (size_t)r * K + c * 8;
    }
    const __half* src[4] = {Ah + (size_t)m0 * K, Al + (size_t)m0 * K,
                            Bh + (size_t)n0 * K, Bl + (size_t)n0 * K};

    auto issue = [&](int i) {
        const uint32_t sbase = sb + (i & 1) * G_STAGE;
        const int k0 = i << 6;
#pragma unroll
        for (int t4 = 0; t4 < 4; t4++) {
            const __half* g = src[t4] + k0;
            const uint32_t st = sbase + t4 * G_TILEB;
#pragma unroll
            for (int it = 0; it < 4; it++) CP16(st + s_off[it], g + g_off[it]);
        }
        asm volatile("cp.async.commit_group;" ::: "memory");
    };

    uint32_t aoff[2], boff[4];
#pragma unroll
    for (int mt = 0; mt < 2; mt++) {
        int row = wm * 32 + mt * 16 + (lane & 15);
        aoff[mt] = (uint32_t)(row * G_ROWB + (lane >> 4) * 16);
    }
#pragma unroll
    for (int ng = 0; ng < 4; ng++) {
        int row = wn * 64 + ng * 16 + (lane & 15);
        boff[ng] = (uint32_t)(2 * G_TILEB + row * G_ROWB + (lane >> 4) * 16);
    }

    float acc[2][8][4];
#pragma unroll
    for (int mt = 0; mt < 2; mt++)
#pragma unroll
        for (int n = 0; n < 8; n++)
#pragma unroll
            for (int e = 0; e < 4; e++) acc[mt][n][e] = 0.f;

    const int niter = K >> 6;
    issue(0);

    for (int i = 0; i < niter; i++) {
        if (i + 1 < niter) {
            issue(i + 1);
            asm volatile("cp.async.wait_group 1;" ::: "memory");
        } else {
            asm volatile("cp.async.wait_group 0;" ::: "memory");
        }
        __syncthreads();

        const uint32_t st = sb + (i & 1) * G_STAGE;
#pragma unroll
        for (int ks = 0; ks < 4; ks++) {
            const uint32_t kadd = ks * 32;
            uint32_t ah[2][4], al[2][4], bh[8][2], bl[8][2];
#pragma unroll
            for (int mt = 0; mt < 2; mt++) {
                LDSM4(ah[mt][0], ah[mt][1], ah[mt][2], ah[mt][3],
                      st + aoff[mt] + kadd);
                LDSM4(al[mt][0], al[mt][1], al[mt][2], al[mt][3],
                      st + G_TILEB + aoff[mt] + kadd);
            }
#pragma unroll
            for (int ng = 0; ng < 4; ng++) {
                uint32_t r0, r1, r2, r3;
                LDSM4(r0, r1, r2, r3, st + boff[ng] + kadd);
                bh[ng * 2][0] = r0; bh[ng * 2][1] = r2;
                bh[ng * 2 + 1][0] = r1; bh[ng * 2 + 1][1] = r3;
                LDSM4(r0, r1, r2, r3, st + G_TILEB + boff[ng] + kadd);
                bl[ng * 2][0] = r0; bl[ng * 2][1] = r2;
                bl[ng * 2 + 1][0] = r1; bl[ng * 2 + 1][1] = r3;
            }
#pragma unroll
            for (int mt = 0; mt < 2; mt++)
#pragma unroll
                for (int n = 0; n < 8; n++) {
                    MMA16816(acc[mt][n], ah[mt], bh[n]);
                    MMA16816(acc[mt][n], al[mt], bh[n]);
                    MMA16816(acc[mt][n], ah[mt], bl[n]);
                }
        }
        __syncthreads();
    }

    const int row_b = m0 + wm * 32 + (lane >> 2);
    const int col_b = n0 + wn * 64 + (lane & 3) * 2;

#pragma unroll
    for (int mt = 0; mt < 2; mt++)
#pragma unroll
        for (int n = 0; n < 8; n++) {
            const int col = col_b + n * 8;
            const int r0_ = row_b + mt * 16;
            const int r1_ = r0_ + 8;
            if (MODE == 0) {
                float* c0 = Cf + (size_t)r0_ * N + col;
                float* c1 = Cf + (size_t)r1_ * N + col;
                c0[0] = acc[mt][n][0] * cscale;
                c0[1] = acc[mt][n][1] * cscale;
                c1[0] = acc[mt][n][2] * cscale;
                c1[1] = acc[mt][n][3] * cscale;
            } else {
                float x0 = acc[mt][n][0] * cscale, y0 = acc[mt][n][1] * cscale;
                float x1 = acc[mt][n][2] * cscale, y1 = acc[mt][n][3] * cscale;
                if (MODE == 1) {
                    int p = (col & 127) >> 1;
                    float c0v = fc[r0_ * 64 + p], s0v = fs[r0_ * 64 + p];
                    float c1v = fc[r1_ * 64 + p], s1v = fs[r1_ * 64 + p];
                    float nx0 = (x0 * c0v - y0 * s0v) * oscale;
                    float ny0 = (x0 * s0v + y0 * c0v) * oscale;
                    float nx1 = (x1 * c1v - y1 * s1v) * oscale;
                    float ny1 = (x1 * s1v + y1 * c1v) * oscale;
                    x0 = nx0; y0 = ny0; x1 = nx1; y1 = ny1;
                }
                uint32_t h0 = pack_h2f(x0, y0), l0 = pack_resid(h0, x0, y0);
                uint32_t h1 = pack_h2f(x1, y1), l1 = pack_resid(h1, x1, y1);
                *(uint32_t*)(Ch + (size_t)r0_ * N + col) = h0;
                *(uint32_t*)(Cl + (size_t)r0_ * N + col) = l0;
                *(uint32_t*)(Ch + (size_t)r1_ * N + col) = h1;
                *(uint32_t*)(Cl + (size_t)r1_ * N + col) = l1;
            }
        }
}

// ---------------------------------------------------------------------------
// fp32 -> fp16 hi/lo split (for x)
// ---------------------------------------------------------------------------
__global__ void split_kernel(const float* __restrict__ in,
                             __half* __restrict__ hi, __half* __restrict__ lo,
                             int n) {
    int i = blockIdx.x * blockDim.x + threadIdx.x;
    if (i >= n) return;
    float v = in[i];
    __half h = __float2half_rn(v);
    hi[i] = h;
    lo[i] = __float2half_rn(v - __half2float(h));
}

// W [K,N] -> hi/lo [N,K] (transpose + split + x64 scale)
__global__ void __launch_bounds__(256) transpose_split(
    const float* __restrict__ W, __half* __restrict__ hi,
    __half* __restrict__ lo, int K, int N) {
    __shared__ float t[32][33];
    const int n0 = blockIdx.x * 32;
    const int k0 = blockIdx.y * 32;
    const int tx = threadIdx.x;
#pragma unroll
    for (int j = threadIdx.y; j < 32; j += 8)
        t[j][tx] = W[(size_t)(k0 + j) * N + n0 + tx];
    __syncthreads();
#pragma unroll
    for (int j = threadIdx.y; j < 32; j += 8) {
        float v = t[tx][j] * WSCALE;
        __half h = __float2half_rn(v);
        size_t o = (size_t)(n0 + j) * K + k0 + tx;
        hi[o] = h;
        lo[o] = __float2half_rn(v - __half2float(h));
    }
}

// ---------------------------------------------------------------------------
// HMMA flash attention, causal, online softmax. BQ=128, BKV=64, 8 warps.
// Full hi/lo splits on Q,K,V,P.
// ---------------------------------------------------------------------------
#define FRSB 272                       // 136 halves per smem row
#define FQ_BYTES (128 * FRSB)          // 34816
#define FKV_TILE (64 * FRSB)           // 17408
#define FSTAGE (4 * FKV_TILE)          // 69632
#define FSMEM (2 * FQ_BYTES + 2 * FSTAGE)  // 208896

__global__ void __launch_bounds__(256, 1)
flash_hmma(const __half* __restrict__ Qh, const __half* __restrict__ Ql,
           const __half* __restrict__ Kh, const __half* __restrict__ Kl,
           const __half* __restrict__ Vh, const __half* __restrict__ Vl,
           __half* __restrict__ Oh, __half* __restrict__ Ol) {
    extern __shared__ char smf[];
    const uint32_t sb = smem_u32(smf);
    const int tid = threadIdx.x, lane = tid & 31, w = tid >> 5;
    const int head = blockIdx.y, kvh = head >> 2;
    const int qt = gridDim.x - 1 - blockIdx.x;
    const int q0 = qt * 128;
    const int nt = (q0 >> 6) + 2;

    // ---- Q tile load (group 1)
#pragma unroll
    for (int it = 0; it < 8; it++) {
        int idx = it * 256 + tid;          // 0..2047
        int r = idx >> 4, c = idx & 15;
        size_t go = (size_t)(q0 + r) * D_MODEL + head * HEAD_DIM + c * 8;
        uint32_t so = (uint32_t)(r * FRSB + c * 16);
        CP16(sb + so, Qh + go);
        CP16(sb + FQ_BYTES + so, Ql + go);
    }
    asm volatile("cp.async.commit_group;" ::: "memory");

    const __half* kvsrc[4] = {Kh, Kl, Vh, Vl};
    auto issue_kv = [&](int t) {
        const int k0 = t << 6;
        const uint32_t stage = sb + 2 * FQ_BYTES + (t & 1) * FSTAGE;
#pragma unroll
        for (int it = 0; it < 16; it++) {
            int idx = it * 256 + tid;      // 0..4095
            int op = idx >> 10;
            int r = (idx >> 4) & 63, c = idx & 15;
            const __half* g = kvsrc[op] + (size_t)(k0 + r) * KVDIM +
                              kvh * HEAD_DIM + c * 8;
            CP16(stage + op * FKV_TILE + r * FRSB + c * 16, g);
        }
        asm volatile("cp.async.commit_group;" ::: "memory");
    };
    issue_kv(0);

    // ldsm base addresses (A frags from Q; B frags K non-trans, V trans)
    const uint32_t qa_h = sb + (w * 16 + (lane & 15)) * FRSB + (lane >> 4) * 16;
    const uint32_t qa_l = qa_h + FQ_BYTES;
    const uint32_t kvoff = (uint32_t)((lane & 15) * FRSB + (lane >> 4) * 16);

    float m_lo = -1e30f, m_hi = -1e30f, l_lo = 0.f, l_hi = 0.f;
    float o_acc[16][4];
#pragma unroll
    for (int nf = 0; nf < 16; nf++)
#pragma unroll
        for (int e = 0; e < 4; e++) o_acc[nf][e] = 0.f;

    const int r_lo = lane >> 2;
    const int row_lo_g = q0 + w * 16 + r_lo;
    const int row_hi_g = row_lo_g + 8;

    for (int t = 0; t < nt; t++) {
        if (t + 1 < nt) {
            issue_kv(t + 1);
            asm volatile("cp.async.wait_group 1;" ::: "memory");
        } else {
            asm volatile("cp.async.wait_group 0;" ::: "memory");
        }
        __syncthreads();

        const uint32_t stage = sb + 2 * FQ_BYTES + (t & 1) * FSTAGE;
        const uint32_t kb = stage + kvoff;
        const uint32_t kbl = kb + FKV_TILE;
        const uint32_t vb = stage + 2 * FKV_TILE + kvoff;
        const uint32_t vbl = vb + FKV_TILE;
        const int k0 = t << 6;

        // ---- S = Q @ K^T (3 split passes), fp32 acc
        float sa[8][4];
#pragma unroll
        for (int nf = 0; nf < 8; nf++)
#pragma unroll
            for (int e = 0; e < 4; e++) sa[nf][e] = 0.f;

#pragma unroll
        for (int ks = 0; ks < 8; ks++) {
            uint32_t ah[4], al[4];
            LDSM4(ah[0], ah[1], ah[2], ah[3], qa_h + ks * 32);
            LDSM4(al[0], al[1], al[2], al[3], qa_l + ks * 32);
#pragma unroll
            for (int ng = 0; ng < 4; ng++) {
                uint32_t h0, h1, h2, h3, l0, l1, l2, l3;
                LDSM4(h0, h1, h2, h3, kb + ng * (16 * FRSB) + ks * 32);
                LDSM4(l0, l1, l2, l3, kbl + ng * (16 * FRSB) + ks * 32);
                uint32_t bh0[2] = {h0, h2}, bh1[2] = {h1, h3};
                uint32_t bl0[2] = {l0, l2}, bl1[2] = {l1, l3};
                MMA16816(sa[2 * ng], ah, bh0);
                MMA16816(sa[2 * ng], al, bh0);
                MMA16816(sa[2 * ng], ah, bl0);
                MMA16816(sa[2 * ng + 1], ah, bh1);
                MMA16816(sa[2 * ng + 1], al, bh1);
                MMA16816(sa[2 * ng + 1], ah, bl1);
            }
        }

        // ---- causal mask (only the last two tiles touch the diagonal)
        if (t >= nt - 2) {
#pragma unroll
            for (int nf = 0; nf < 8; nf++) {
                int cb = k0 + nf * 8 + (lane & 3) * 2;
                if (cb > row_lo_g) sa[nf][0] = -1e30f;
                if (cb + 1 > row_lo_g) sa[nf][1] = -1e30f;
                if (cb > row_hi_g) sa[nf][2] = -1e30f;
                if (cb + 1 > row_hi_g) sa[nf][3] = -1e30f;
            }
        }

        // ---- online softmax
        float tm_lo = -1e30f, tm_hi = -1e30f;
#pragma unroll
        for (int nf = 0; nf < 8; nf++) {
            tm_lo = fmaxf(tm_lo, fmaxf(sa[nf][0], sa[nf][1]));
            tm_hi = fmaxf(tm_hi, fmaxf(sa[nf][2], sa[nf][3]));
        }
        tm_lo = fmaxf(tm_lo, __shfl_xor_sync(0xffffffffu, tm_lo, 1));
        tm_lo = fmaxf(tm_lo, __shfl_xor_sync(0xffffffffu, tm_lo, 2));
        tm_hi = fmaxf(tm_hi, __shfl_xor_sync(0xffffffffu, tm_hi, 1));
        tm_hi = fmaxf(tm_hi, __shfl_xor_sync(0xffffffffu, tm_hi, 2));

        float mn_lo = fmaxf(m_lo, tm_lo), mn_hi = fmaxf(m_hi, tm_hi);
        float al_lo = __expf(m_lo - mn_lo), al_hi = __expf(m_hi - mn_hi);
        m_lo = mn_lo; m_hi = mn_hi;

        float sum_lo = 0.f, sum_hi = 0.f;
#pragma unroll
        for (int nf = 0; nf < 8; nf++) {
            sa[nf][0] = __expf(sa[nf][0] - mn_lo);
            sa[nf][1] = __expf(sa[nf][1] - mn_lo);
            sa[nf][2] = __expf(sa[nf][2] - mn_hi);
            sa[nf][3] = __expf(sa[nf][3] - mn_hi);
            sum_lo += sa[nf][0] + sa[nf][1];
            sum_hi += sa[nf][2] + sa[nf][3];
        }
        sum_lo += __shfl_xor_sync(0xffffffffu, sum_lo, 1);
        sum_lo += __shfl_xor_sync(0xffffffffu, sum_lo, 2);
        sum_hi += __shfl_xor_sync(0xffffffffu, sum_hi, 1);
        sum_hi += __shfl_xor_sync(0xffffffffu, sum_hi, 2);
        l_lo = l_lo * al_lo + sum_lo;
        l_hi = l_hi * al_hi + sum_hi;

#pragma unroll
        for (int nf = 0; nf < 16; nf++) {
            o_acc[nf][0] *= al_lo; o_acc[nf][1] *= al_lo;
            o_acc[nf][2] *= al_hi; o_acc[nf][3] *= al_hi;
        }

        // ---- P split into A-fragments (hi + residual)
        uint32_t pah[4][4], pal[4][4];
#pragma unroll
        for (int j = 0; j < 4; j++) {
            pah[j][0] = pack_h2f(sa[2 * j][0], sa[2 * j][1]);
            pal[j][0] = pack_resid(pah[j][0], sa[2 * j][0], sa[2 * j][1]);
            pah[j][1] = pack_h2f(sa[2 * j][2], sa[2 * j][3]);
            pal[j][1] = pack_resid(pah[j][1], sa[2 * j][2], sa[2 * j][3]);
            pah[j][2] = pack_h2f(sa[2 * j + 1][0], sa[2 * j + 1][1]);
            pal[j][2] = pack_resid(pah[j][2], sa[2 * j + 1][0], sa[2 * j + 1][1]);
            pah[j][3] = pack_h2f(sa[2 * j + 1][2], sa[2 * j + 1][3]);
            pal[j][3] = pack_resid(pah[j][3], sa[2 * j + 1][2], sa[2 * j + 1][3]);
        }

        // ---- O += P @ V (3 split passes), V via ldmatrix.trans
#pragma unroll
        for (int j = 0; j < 4; j++) {
#pragma unroll
            for (int dg = 0; dg < 8; dg++) {
                uint32_t h0, h1, h2, h3, l0, l1, l2, l3;
                LDSM4T(h0, h1, h2, h3, vb + j * (16 * FRSB) + dg * 32);
                LDSM4T(l0, l1, l2, l3, vbl + j * (16 * FRSB) + dg * 32);
                uint32_t bh0[2] = {h0, h1}, bh1[2] = {h2, h3};
                uint32_t bl0[2] = {l0, l1}, bl1[2] = {l2, l3};
                MMA16816(o_acc[2 * dg], pah[j], bh0);
                MMA16816(o_acc[2 * dg], pal[j], bh0);
                MMA16816(o_acc[2 * dg], pah[j], bl0);
                MMA16816(o_acc[2 * dg + 1], pah[j], bh1);
                MMA16816(o_acc[2 * dg + 1], pal[j], bh1);
                MMA16816(o_acc[2 * dg + 1], pah[j], bl1);
            }
        }
        __syncthreads();
    }

    // ---- epilogue: normalize, split, write hi/lo
    const float inv_lo = 1.f / l_lo, inv_hi = 1.f / l_hi;
#pragma unroll
    for (int nf = 0; nf < 16; nf++) {
        int col = head * HEAD_DIM + nf * 8 + (lane & 3) * 2;
        float o0 = o_acc[nf][0] * inv_lo, o1 = o_acc[nf][1] * inv_lo;
        float o2 = o_acc[nf][2] * inv_hi, o3 = o_acc[nf][3] * inv_hi;
        uint32_t h0 = pack_h2f(o0, o1), L0 = pack_resid(h0, o0, o1);
        uint32_t h1 = pack_h2f(o2, o3), L1 = pack_resid(h1, o2, o3);
        *(uint32_t*)(Oh + (size_t)row_lo_g * D_MODEL + col) = h0;
        *(uint32_t*)(Ol + (size_t)row_lo_g * D_MODEL + col) = L0;
        *(uint32_t*)(Oh + (size_t)row_hi_g * D_MODEL + col) = h1;
        *(uint32_t*)(Ol + (size_t)row_hi_g * D_MODEL + col) = L1;
    }
}

// ---------------------------------------------------------------------------
// Launch
// ---------------------------------------------------------------------------
extern "C" void kernel_launch(void* const* d_in, const int* in_sizes, int n_in,
                              void* d_out, int out_size) {
    const float* x  = (const float*)d_in[0];
    const float* fc = (const float*)d_in[1];
    const float* fs = (const float*)d_in[2];
    const float* wq = (const float*)d_in[4];
    const float* wk = (const float*)d_in[5];
    const float* wv = (const float*)d_in[6];
    const float* wo = (const float*)d_in[7];
    float* out = (float*)d_out;

    __half *xh, *xl, *qh, *ql, *kh, *kl, *vh, *vl, *aoh, *aol;
    __half *wqh, *wql, *wkh, *wkl, *wvh, *wvl, *woh, *wol;
    cudaGetSymbolAddress((void**)&xh,  g_xh);
    cudaGetSymbolAddress((void**)&xl,  g_xl);
    cudaGetSymbolAddress((void**)&qh,  g_qh);
    cudaGetSymbolAddress((void**)&ql,  g_ql);
    cudaGetSymbolAddress((void**)&kh,  g_kh);
    cudaGetSymbolAddress((void**)&kl,  g_kl);
    cudaGetSymbolAddress((void**)&vh,  g_vh);
    cudaGetSymbolAddress((void**)&vl,  g_vl);
    cudaGetSymbolAddress((void**)&aoh, g_aoh);
    cudaGetSymbolAddress((void**)&aol, g_aol);
    cudaGetSymbolAddress((void**)&wqh, g_wqh);
    cudaGetSymbolAddress((void**)&wql, g_wql);
    cudaGetSymbolAddress((void**)&wkh, g_wkh);
    cudaGetSymbolAddress((void**)&wkl, g_wkl);
    cudaGetSymbolAddress((void**)&wvh, g_wvh);
    cudaGetSymbolAddress((void**)&wvl, g_wvl);
    cudaGetSymbolAddress((void**)&woh, g_woh);
    cudaGetSymbolAddress((void**)&wol, g_wol);

    cudaFuncSetAttribute(gemm_hmma_split<0>,
                         cudaFuncAttributeMaxDynamicSharedMemorySize, G_SMEM);
    cudaFuncSetAttribute(gemm_hmma_split<1>,
                         cudaFuncAttributeMaxDynamicSharedMemorySize, G_SMEM);
    cudaFuncSetAttribute(gemm_hmma_split<2>,
                         cudaFuncAttributeMaxDynamicSharedMemorySize, G_SMEM);
    cudaFuncSetAttribute(flash_hmma,
                         cudaFuncAttributeMaxDynamicSharedMemorySize, FSMEM);

    // Conversions
    split_kernel<<<(S_LEN * D_MODEL + 255) / 256, 256>>>(x, xh, xl, S_LEN * D_MODEL);
    transpose_split<<<dim3(D_MODEL / 32, D_MODEL / 32), dim3(32, 8)>>>(wq, wqh, wql, D_MODEL, D_MODEL);
    transpose_split<<<dim3(KVDIM / 32,  D_MODEL / 32), dim3(32, 8)>>>(wk, wkh, wkl, D_MODEL, KVDIM);
    transpose_split<<<dim3(KVDIM / 32,  D_MODEL / 32), dim3(32, 8)>>>(wv, wvh, wvl, D_MODEL, KVDIM);
    transpose_split<<<dim3(D_MODEL / 32, D_MODEL / 32), dim3(32, 8)>>>(wo, woh, wol, D_MODEL, D_MODEL);

    // Projections with fused rope/split epilogues
    gemm_hmma_split<1><<<dim3(D_MODEL / 128, S_LEN / 128), 256, G_SMEM>>>(
        xh, xl, wqh, wql, nullptr, qh, ql, fc, fs,
        S_LEN, D_MODEL, D_MODEL, INV_WSCALE, QK_SCALE);
    gemm_hmma_split<1><<<dim3(KVDIM / 128, S_LEN / 128), 256, G_SMEM>>>(
        xh, xl, wkh, wkl, nullptr, kh, kl, fc, fs,
        S_LEN, KVDIM, D_MODEL, INV_WSCALE, 1.0f);
    gemm_hmma_split<2><<<dim3(KVDIM / 128, S_LEN / 128), 256, G_SMEM>>>(
        xh, xl, wvh, wvl, nullptr, vh, vl, nullptr, nullptr,
        S_LEN, KVDIM, D_MODEL, INV_WSCALE, 1.0f);

    // HMMA flash attention
    flash_hmma<<<dim3(S_LEN / 128, N_HEADS), 256, FSMEM>>>(
        qh, ql, kh, kl, vh, vl, aoh, aol);

    // Output projection (fp32 out)
    gemm_hmma_split<0><<<dim3(D_MODEL / 128, S_LEN / 128), 256, G_SMEM>>>(
        aoh, aol, woh, wol, out, nullptr, nullptr, nullptr, nullptr,
        S_LEN, D_MODEL, D_MODEL, INV_WSCALE, 1.0f);
}

// round 5
// speedup vs baseline: 3.1510x; 1.0145x over previous
#include <cuda_runtime.h>
#include <cuda_fp16.h>
#include <cstdint>

// Problem constants
#define S_LEN 2048
#define D_MODEL 4096
#define N_HEADS 32
#define N_KV 8
#define HEAD_DIM 128
#define KVDIM (N_KV * HEAD_DIM)   // 1024

#define WSCALE 64.0f
#define INV_WSCALE (1.0f / 64.0f)
#define QK_SCALE 0.08838834764831845f  // 1/sqrt(128)

// ---------------------------------------------------------------------------
// Scratch (device globals)
// ---------------------------------------------------------------------------
__device__ __align__(128) __half g_xh[S_LEN * D_MODEL];
__device__ __align__(128) __half g_xl[S_LEN * D_MODEL];
__device__ __align__(128) __half g_qh[S_LEN * D_MODEL];
__device__ __align__(128) __half g_ql[S_LEN * D_MODEL];
__device__ __align__(128) __half g_kh[S_LEN * KVDIM];
__device__ __align__(128) __half g_kl[S_LEN * KVDIM];
__device__ __align__(128) __half g_vh[S_LEN * KVDIM];
__device__ __align__(128) __half g_vl[S_LEN * KVDIM];
__device__ __align__(128) __half g_aoh[S_LEN * D_MODEL];
__device__ __align__(128) __half g_aol[S_LEN * D_MODEL];
__device__ __align__(128) __half g_wqh[D_MODEL * D_MODEL];  // [N,K], x64
__device__ __align__(128) __half g_wql[D_MODEL * D_MODEL];
__device__ __align__(128) __half g_wkh[KVDIM * D_MODEL];
__device__ __align__(128) __half g_wkl[KVDIM * D_MODEL];
__device__ __align__(128) __half g_wvh[KVDIM * D_MODEL];
__device__ __align__(128) __half g_wvl[KVDIM * D_MODEL];
__device__ __align__(128) __half g_woh[D_MODEL * D_MODEL];
__device__ __align__(128) __half g_wol[D_MODEL * D_MODEL];

// ---------------------------------------------------------------------------
// Helpers
// ---------------------------------------------------------------------------
__device__ __forceinline__ uint32_t smem_u32(const void* p) {
    uint32_t a;
    asm("{ .reg .u64 t; cvta.to.shared.u64 t, %1; cvt.u32.u64 %0, t; }"
        : "=r"(a) : "l"(p));
    return a;
}
__device__ __forceinline__ uint32_t pack_h2f(float a, float b) {
    __half2 h = __floats2half2_rn(a, b);
    return *reinterpret_cast<uint32_t*>(&h);
}
__device__ __forceinline__ uint32_t pack_resid(uint32_t h, float a, float b) {
    __half2 hh = *reinterpret_cast<__half2*>(&h);
    float2 f = __half22float2(hh);
    return pack_h2f(a - f.x, b - f.y);
}

#define LDSM4(r0, r1, r2, r3, addr)                                           \
    asm volatile("ldmatrix.sync.aligned.m8n8.x4.shared.b16 {%0,%1,%2,%3}, [%4];" \
                 : "=r"(r0), "=r"(r1), "=r"(r2), "=r"(r3) : "r"(addr))
#define LDSM4T(r0, r1, r2, r3, addr)                                          \
    asm volatile("ldmatrix.sync.aligned.m8n8.x4.trans.shared.b16 {%0,%1,%2,%3}, [%4];" \
                 : "=r"(r0), "=r"(r1), "=r"(r2), "=r"(r3) : "r"(addr))
#define MMA16816(d, a, b)                                                     \
    asm volatile(                                                             \
        "mma.sync.aligned.m16n8k16.row.col.f32.f16.f16.f32 "                  \
        "{%0,%1,%2,%3}, {%4,%5,%6,%7}, {%8,%9}, {%0,%1,%2,%3};"               \
        : "+f"((d)[0]), "+f"((d)[1]), "+f"((d)[2]), "+f"((d)[3])              \
        : "r"((a)[0]), "r"((a)[1]), "r"((a)[2]), "r"((a)[3]),                 \
          "r"((b)[0]), "r"((b)[1]))
#define CP16(s, g)                                                            \
    asm volatile("cp.async.cg.shared.global [%0], [%1], 16;"                  \
                 :: "r"(s), "l"(g) : "memory")

// ---------------------------------------------------------------------------
// HMMA GEMM with fp16 hi/lo split.
// Epilogue modes: 0 = fp32 out, 1 = rope+scale+split out, 2 = split out.
// Single __syncthreads per K-iter (wait -> sync -> issue -> compute).
// ---------------------------------------------------------------------------
#define G_ROWB 144
#define G_TILEB (128 * G_ROWB)
#define G_STAGE (4 * G_TILEB)
#define G_SMEM (2 * G_STAGE)

struct GemmArgs {
    const __half *Ah, *Al, *Bh, *Bl;
    float* Cf;
    __half *Ch, *Cl;
    const float *fc, *fs;
    int N;          // output width
    float cscale, oscale;
    int mode;
};

__device__ __forceinline__ void gemm_body(const GemmArgs& ga, int m0, int n0,
                                          int K, char* smem) {
    const uint32_t sb = smem_u32(smem);
    const int tid = threadIdx.x;
    const int lane = tid & 31;
    const int wid = tid >> 5;
    const int wm = wid & 3;
    const int wn = wid >> 2;

    uint32_t s_off[4];
    size_t g_off[4];
#pragma unroll
    for (int it = 0; it < 4; it++) {
        int idx = it * 256 + tid;
        int r = idx >> 3;
        int c = idx & 7;
        s_off[it] = (uint32_t)(r * G_ROWB + c * 16);
        g_off[it] = (size_t)r * K + c * 8;
    }
    const __half* src[4] = {ga.Ah + (size_t)m0 * K, ga.Al + (size_t)m0 * K,
                            ga.Bh + (size_t)n0 * K, ga.Bl + (size_t)n0 * K};

    auto issue = [&](int i) {
        const uint32_t sbase = sb + (i & 1) * G_STAGE;
        const int k0 = i << 6;
#pragma unroll
        for (int t4 = 0; t4 < 4; t4++) {
            const __half* g = src[t4] + k0;
            const uint32_t st = sbase + t4 * G_TILEB;
#pragma unroll
            for (int it = 0; it < 4; it++) CP16(st + s_off[it], g + g_off[it]);
        }
        asm volatile("cp.async.commit_group;" ::: "memory");
    };

    uint32_t aoff[2], boff[4];
#pragma unroll
    for (int mt = 0; mt < 2; mt++) {
        int row = wm * 32 + mt * 16 + (lane & 15);
        aoff[mt] = (uint32_t)(row * G_ROWB + (lane >> 4) * 16);
    }
#pragma unroll
    for (int ng = 0; ng < 4; ng++) {
        int row = wn * 64 + ng * 16 + (lane & 15);
        boff[ng] = (uint32_t)(2 * G_TILEB + row * G_ROWB + (lane >> 4) * 16);
    }

    float acc[2][8][4];
#pragma unroll
    for (int mt = 0; mt < 2; mt++)
#pragma unroll
        for (int n = 0; n < 8; n++)
#pragma unroll
            for (int e = 0; e < 4; e++) acc[mt][n][e] = 0.f;

    const int niter = K >> 6;
    issue(0);

    for (int i = 0; i < niter; i++) {
        asm volatile("cp.async.wait_group 0;" ::: "memory");
        __syncthreads();
        if (i + 1 < niter) issue(i + 1);

        const uint32_t st = sb + (i & 1) * G_STAGE;
#pragma unroll
        for (int ks = 0; ks < 4; ks++) {
            const uint32_t kadd = ks * 32;
            uint32_t ah[2][4], al[2][4], bh[8][2], bl[8][2];
#pragma unroll
            for (int mt = 0; mt < 2; mt++) {
                LDSM4(ah[mt][0], ah[mt][1], ah[mt][2], ah[mt][3],
                      st + aoff[mt] + kadd);
                LDSM4(al[mt][0], al[mt][1], al[mt][2], al[mt][3],
                      st + G_TILEB + aoff[mt] + kadd);
            }
#pragma unroll
            for (int ng = 0; ng < 4; ng++) {
                uint32_t r0, r1, r2, r3;
                LDSM4(r0, r1, r2, r3, st + boff[ng] + kadd);
                bh[ng * 2][0] = r0; bh[ng * 2][1] = r2;
                bh[ng * 2 + 1][0] = r1; bh[ng * 2 + 1][1] = r3;
                LDSM4(r0, r1, r2, r3, st + G_TILEB + boff[ng] + kadd);
                bl[ng * 2][0] = r0; bl[ng * 2][1] = r2;
                bl[ng * 2 + 1][0] = r1; bl[ng * 2 + 1][1] = r3;
            }
#pragma unroll
            for (int mt = 0; mt < 2; mt++)
#pragma unroll
                for (int n = 0; n < 8; n++) {
                    MMA16816(acc[mt][n], ah[mt], bh[n]);
                    MMA16816(acc[mt][n], al[mt], bh[n]);
                    MMA16816(acc[mt][n], ah[mt], bl[n]);
                }
        }
    }

    const int N = ga.N;
    const int row_b = m0 + wm * 32 + (lane >> 2);
    const int col_b = n0 + wn * 64 + (lane & 3) * 2;

#pragma unroll
    for (int mt = 0; mt < 2; mt++)
#pragma unroll
        for (int n = 0; n < 8; n++) {
            const int col = col_b + n * 8;
            const int r0_ = row_b + mt * 16;
            const int r1_ = r0_ + 8;
            if (ga.mode == 0) {
                float* c0 = ga.Cf + (size_t)r0_ * N + col;
                float* c1 = ga.Cf + (size_t)r1_ * N + col;
                c0[0] = acc[mt][n][0] * ga.cscale;
                c0[1] = acc[mt][n][1] * ga.cscale;
                c1[0] = acc[mt][n][2] * ga.cscale;
                c1[1] = acc[mt][n][3] * ga.cscale;
            } else {
                float x0 = acc[mt][n][0] * ga.cscale, y0 = acc[mt][n][1] * ga.cscale;
                float x1 = acc[mt][n][2] * ga.cscale, y1 = acc[mt][n][3] * ga.cscale;
                if (ga.mode == 1) {
                    int p = (col & 127) >> 1;
                    float c0v = ga.fc[r0_ * 64 + p], s0v = ga.fs[r0_ * 64 + p];
                    float c1v = ga.fc[r1_ * 64 + p], s1v = ga.fs[r1_ * 64 + p];
                    float nx0 = (x0 * c0v - y0 * s0v) * ga.oscale;
                    float ny0 = (x0 * s0v + y0 * c0v) * ga.oscale;
                    float nx1 = (x1 * c1v - y1 * s1v) * ga.oscale;
                    float ny1 = (x1 * s1v + y1 * c1v) * ga.oscale;
                    x0 = nx0; y0 = ny0; x1 = nx1; y1 = ny1;
                }
                uint32_t h0 = pack_h2f(x0, y0), l0 = pack_resid(h0, x0, y0);
                uint32_t h1 = pack_h2f(x1, y1), l1 = pack_resid(h1, x1, y1);
                *(uint32_t*)(ga.Ch + (size_t)r0_ * N + col) = h0;
                *(uint32_t*)(ga.Cl + (size_t)r0_ * N + col) = l0;
                *(uint32_t*)(ga.Ch + (size_t)r1_ * N + col) = h1;
                *(uint32_t*)(ga.Cl + (size_t)r1_ * N + col) = l1;
            }
        }
}

// Fused QKV projection: grid.x = 48 (32 Q blocks, 8 K, 8 V), grid.y = 16 rows.
__global__ void __launch_bounds__(256, 1)
qkv_gemm(const __half* __restrict__ xh, const __half* __restrict__ xl,
         const float* __restrict__ fc, const float* __restrict__ fs,
         const __half* __restrict__ wqh, const __half* __restrict__ wql,
         const __half* __restrict__ wkh, const __half* __restrict__ wkl,
         const __half* __restrict__ wvh, const __half* __restrict__ wvl,
         __half* __restrict__ qh, __half* __restrict__ ql,
         __half* __restrict__ kh, __half* __restrict__ kl,
         __half* __restrict__ vh, __half* __restrict__ vl) {
    extern __shared__ char smem[];
    const int bx = blockIdx.x;
    GemmArgs ga;
    ga.Ah = xh; ga.Al = xl;
    ga.fc = fc; ga.fs = fs;
    ga.Cf = nullptr;
    ga.cscale = INV_WSCALE;
    int n0;
    if (bx < 32) {
        ga.Bh = wqh; ga.Bl = wql; ga.Ch = qh; ga.Cl = ql;
        ga.N = D_MODEL; ga.mode = 1; ga.oscale = QK_SCALE;
        n0 = bx * 128;
    } else if (bx < 40) {
        ga.Bh = wkh; ga.Bl = wkl; ga.Ch = kh; ga.Cl = kl;
        ga.N = KVDIM; ga.mode = 1; ga.oscale = 1.0f;
        n0 = (bx - 32) * 128;
    } else {
        ga.Bh = wvh; ga.Bl = wvl; ga.Ch = vh; ga.Cl = vl;
        ga.N = KVDIM; ga.mode = 2; ga.oscale = 1.0f;
        n0 = (bx - 40) * 128;
    }
    gemm_body(ga, blockIdx.y * 128, n0, D_MODEL, smem);
}

// Output projection (fp32 out)
__global__ void __launch_bounds__(256, 1)
wo_gemm(const __half* __restrict__ aoh, const __half* __restrict__ aol,
        const __half* __restrict__ woh, const __half* __restrict__ wol,
        float* __restrict__ out) {
    extern __shared__ char smem[];
    GemmArgs ga;
    ga.Ah = aoh; ga.Al = aol; ga.Bh = woh; ga.Bl = wol;
    ga.Cf = out; ga.Ch = nullptr; ga.Cl = nullptr;
    ga.fc = nullptr; ga.fs = nullptr;
    ga.N = D_MODEL; ga.cscale = INV_WSCALE; ga.oscale = 1.0f; ga.mode = 0;
    gemm_body(ga, blockIdx.y * 128, blockIdx.x * 128, D_MODEL, smem);
}

// ---------------------------------------------------------------------------
// Conversions
// ---------------------------------------------------------------------------
__global__ void split_kernel(const float* __restrict__ in,
                             __half* __restrict__ hi, __half* __restrict__ lo,
                             int n) {
    int i = blockIdx.x * blockDim.x + threadIdx.x;
    if (i >= n) return;
    float v = in[i];
    __half h = __float2half_rn(v);
    hi[i] = h;
    lo[i] = __float2half_rn(v - __half2float(h));
}

// All 4 weight transposes in one launch; z selects the weight.
__global__ void __launch_bounds__(256) transpose_split_all(
    const float* __restrict__ wq, const float* __restrict__ wk,
    const float* __restrict__ wv, const float* __restrict__ wo,
    __half* __restrict__ wqh, __half* __restrict__ wql,
    __half* __restrict__ wkh, __half* __restrict__ wkl,
    __half* __restrict__ wvh, __half* __restrict__ wvl,
    __half* __restrict__ woh, __half* __restrict__ wol) {
    const int z = blockIdx.z;
    const float* W;
    __half *hi, *lo;
    int N;
    if (z == 0)      { W = wq; hi = wqh; lo = wql; N = D_MODEL; }
    else if (z == 1) { W = wk; hi = wkh; lo = wkl; N = KVDIM; }
    else if (z == 2) { W = wv; hi = wvh; lo = wvl; N = KVDIM; }
    else             { W = wo; hi = woh; lo = wol; N = D_MODEL; }
    const int n0 = blockIdx.x * 32;
    if (n0 >= N) return;
    const int k0 = blockIdx.y * 32;
    const int K = D_MODEL;

    __shared__ float t[32][33];
    const int tx = threadIdx.x;
#pragma unroll
    for (int j = threadIdx.y; j < 32; j += 8)
        t[j][tx] = W[(size_t)(k0 + j) * N + n0 + tx];
    __syncthreads();
#pragma unroll
    for (int j = threadIdx.y; j < 32; j += 8) {
        float v = t[tx][j] * WSCALE;
        __half h = __float2half_rn(v);
        size_t o = (size_t)(n0 + j) * K + k0 + tx;
        hi[o] = h;
        lo[o] = __float2half_rn(v - __half2float(h));
    }
}

// ---------------------------------------------------------------------------
// HMMA flash attention, causal, online softmax. BQ=128, BKV=64, 8 warps.
// Single sync per KV tile.
// ---------------------------------------------------------------------------
#define FRSB 272
#define FQ_BYTES (128 * FRSB)
#define FKV_TILE (64 * FRSB)
#define FSTAGE (4 * FKV_TILE)
#define FSMEM (2 * FQ_BYTES + 2 * FSTAGE)

__global__ void __launch_bounds__(256, 1)
flash_hmma(const __half* __restrict__ Qh, const __half* __restrict__ Ql,
           const __half* __restrict__ Kh, const __half* __restrict__ Kl,
           const __half* __restrict__ Vh, const __half* __restrict__ Vl,
           __half* __restrict__ Oh, __half* __restrict__ Ol) {
    extern __shared__ char smf[];
    const uint32_t sb = smem_u32(smf);
    const int tid = threadIdx.x, lane = tid & 31, w = tid >> 5;
    const int head = blockIdx.y, kvh = head >> 2;
    const int qt = gridDim.x - 1 - blockIdx.x;
    const int q0 = qt * 128;
    const int nt = (q0 >> 6) + 2;

#pragma unroll
    for (int it = 0; it < 8; it++) {
        int idx = it * 256 + tid;
        int r = idx >> 4, c = idx & 15;
        size_t go = (size_t)(q0 + r) * D_MODEL + head * HEAD_DIM + c * 8;
        uint32_t so = (uint32_t)(r * FRSB + c * 16);
        CP16(sb + so, Qh + go);
        CP16(sb + FQ_BYTES + so, Ql + go);
    }

    const __half* kvsrc[4] = {Kh, Kl, Vh, Vl};
    auto issue_kv = [&](int t) {
        const int k0 = t << 6;
        const uint32_t stage = sb + 2 * FQ_BYTES + (t & 1) * FSTAGE;
#pragma unroll
        for (int it = 0; it < 16; it++) {
            int idx = it * 256 + tid;
            int op = idx >> 10;
            int r = (idx >> 4) & 63, c = idx & 15;
            const __half* g = kvsrc[op] + (size_t)(k0 + r) * KVDIM +
                              kvh * HEAD_DIM + c * 8;
            CP16(stage + op * FKV_TILE + r * FRSB + c * 16, g);
        }
        asm volatile("cp.async.commit_group;" ::: "memory");
    };
    issue_kv(0);   // Q loads ride in group 0 as well

    const uint32_t qa_h = sb + (w * 16 + (lane & 15)) * FRSB + (lane >> 4) * 16;
    const uint32_t qa_l = qa_h + FQ_BYTES;
    const uint32_t kvoff = (uint32_t)((lane & 15) * FRSB + (lane >> 4) * 16);

    float m_lo = -1e30f, m_hi = -1e30f, l_lo = 0.f, l_hi = 0.f;
    float o_acc[16][4];
#pragma unroll
    for (int nf = 0; nf < 16; nf++)
#pragma unroll
        for (int e = 0; e < 4; e++) o_acc[nf][e] = 0.f;

    const int row_lo_g = q0 + w * 16 + (lane >> 2);
    const int row_hi_g = row_lo_g + 8;

    for (int t = 0; t < nt; t++) {
        asm volatile("cp.async.wait_group 0;" ::: "memory");
        __syncthreads();
        if (t + 1 < nt) issue_kv(t + 1);

        const uint32_t stage = sb + 2 * FQ_BYTES + (t & 1) * FSTAGE;
        const uint32_t kb = stage + kvoff;
        const uint32_t kbl = kb + FKV_TILE;
        const uint32_t vb = stage + 2 * FKV_TILE + kvoff;
        const uint32_t vbl = vb + FKV_TILE;
        const int k0 = t << 6;

        float sa[8][4];
#pragma unroll
        for (int nf = 0; nf < 8; nf++)
#pragma unroll
            for (int e = 0; e < 4; e++) sa[nf][e] = 0.f;

#pragma unroll
        for (int ks = 0; ks < 8; ks++) {
            uint32_t ah[4], al[4];
            LDSM4(ah[0], ah[1], ah[2], ah[3], qa_h + ks * 32);
            LDSM4(al[0], al[1], al[2], al[3], qa_l + ks * 32);
#pragma unroll
            for (int ng = 0; ng < 4; ng++) {
                uint32_t h0, h1, h2, h3, l0, l1, l2, l3;
                LDSM4(h0, h1, h2, h3, kb + ng * (16 * FRSB) + ks * 32);
                LDSM4(l0, l1, l2, l3, kbl + ng * (16 * FRSB) + ks * 32);
                uint32_t bh0[2] = {h0, h2}, bh1[2] = {h1, h3};
                uint32_t bl0[2] = {l0, l2}, bl1[2] = {l1, l3};
                MMA16816(sa[2 * ng], ah, bh0);
                MMA16816(sa[2 * ng], al, bh0);
                MMA16816(sa[2 * ng], ah, bl0);
                MMA16816(sa[2 * ng + 1], ah, bh1);
                MMA16816(sa[2 * ng + 1], al, bh1);
                MMA16816(sa[2 * ng + 1], ah, bl1);
            }
        }

        if (t >= nt - 2) {
#pragma unroll
            for (int nf = 0; nf < 8; nf++) {
                int cb = k0 + nf * 8 + (lane & 3) * 2;
                if (cb > row_lo_g) sa[nf][0] = -1e30f;
                if (cb + 1 > row_lo_g) sa[nf][1] = -1e30f;
                if (cb > row_hi_g) sa[nf][2] = -1e30f;
                if (cb + 1 > row_hi_g) sa[nf][3] = -1e30f;
            }
        }

        float tm_lo = -1e30f, tm_hi = -1e30f;
#pragma unroll
        for (int nf = 0; nf < 8; nf++) {
            tm_lo = fmaxf(tm_lo, fmaxf(sa[nf][0], sa[nf][1]));
            tm_hi = fmaxf(tm_hi, fmaxf(sa[nf][2], sa[nf][3]));
        }
        tm_lo = fmaxf(tm_lo, __shfl_xor_sync(0xffffffffu, tm_lo, 1));
        tm_lo = fmaxf(tm_lo, __shfl_xor_sync(0xffffffffu, tm_lo, 2));
        tm_hi = fmaxf(tm_hi, __shfl_xor_sync(0xffffffffu, tm_hi, 1));
        tm_hi = fmaxf(tm_hi, __shfl_xor_sync(0xffffffffu, tm_hi, 2));

        float mn_lo = fmaxf(m_lo, tm_lo), mn_hi = fmaxf(m_hi, tm_hi);
        float al_lo = __expf(m_lo - mn_lo), al_hi = __expf(m_hi - mn_hi);
        m_lo = mn_lo; m_hi = mn_hi;

        float sum_lo = 0.f, sum_hi = 0.f;
#pragma unroll
        for (int nf = 0; nf < 8; nf++) {
            sa[nf][0] = __expf(sa[nf][0] - mn_lo);
            sa[nf][1] = __expf(sa[nf][1] - mn_lo);
            sa[nf][2] = __expf(sa[nf][2] - mn_hi);
            sa[nf][3] = __expf(sa[nf][3] - mn_hi);
            sum_lo += sa[nf][0] + sa[nf][1];
            sum_hi += sa[nf][2] + sa[nf][3];
        }
        sum_lo += __shfl_xor_sync(0xffffffffu, sum_lo, 1);
        sum_lo += __shfl_xor_sync(0xffffffffu, sum_lo, 2);
        sum_hi += __shfl_xor_sync(0xffffffffu, sum_hi, 1);
        sum_hi += __shfl_xor_sync(0xffffffffu, sum_hi, 2);
        l_lo = l_lo * al_lo + sum_lo;
        l_hi = l_hi * al_hi + sum_hi;

#pragma unroll
        for (int nf = 0; nf < 16; nf++) {
            o_acc[nf][0] *= al_lo; o_acc[nf][1] *= al_lo;
            o_acc[nf][2] *= al_hi; o_acc[nf][3] *= al_hi;
        }

        uint32_t pah[4][4], pal[4][4];
#pragma unroll
        for (int j = 0; j < 4; j++) {
            pah[j][0] = pack_h2f(sa[2 * j][0], sa[2 * j][1]);
            pal[j][0] = pack_resid(pah[j][0], sa[2 * j][0], sa[2 * j][1]);
            pah[j][1] = pack_h2f(sa[2 * j][2], sa[2 * j][3]);
            pal[j][1] = pack_resid(pah[j][1], sa[2 * j][2], sa[2 * j][3]);
            pah[j][2] = pack_h2f(sa[2 * j + 1][0], sa[2 * j + 1][1]);
            pal[j][2] = pack_resid(pah[j][2], sa[2 * j + 1][0], sa[2 * j + 1][1]);
            pah[j][3] = pack_h2f(sa[2 * j + 1][2], sa[2 * j + 1][3]);
            pal[j][3] = pack_resid(pah[j][3], sa[2 * j + 1][2], sa[2 * j + 1][3]);
        }

#pragma unroll
        for (int j = 0; j < 4; j++) {
#pragma unroll
            for (int dg = 0; dg < 8; dg++) {
                uint32_t h0, h1, h2, h3, l0, l1, l2, l3;
                LDSM4T(h0, h1, h2, h3, vb + j * (16 * FRSB) + dg * 32);
                LDSM4T(l0, l1, l2, l3, vbl + j * (16 * FRSB) + dg * 32);
                uint32_t bh0[2] = {h0, h1}, bh1[2] = {h2, h3};
                uint32_t bl0[2] = {l0, l1}, bl1[2] = {l2, l3};
                MMA16816(o_acc[2 * dg], pah[j], bh0);
                MMA16816(o_acc[2 * dg], pal[j], bh0);
                MMA16816(o_acc[2 * dg], pah[j], bl0);
                MMA16816(o_acc[2 * dg + 1], pah[j], bh1);
                MMA16816(o_acc[2 * dg + 1], pal[j], bh1);
                MMA16816(o_acc[2 * dg + 1], pah[j], bl1);
            }
        }
    }

    const float inv_lo = 1.f / l_lo, inv_hi = 1.f / l_hi;
#pragma unroll
    for (int nf = 0; nf < 16; nf++) {
        int col = head * HEAD_DIM + nf * 8 + (lane & 3) * 2;
        float o0 = o_acc[nf][0] * inv_lo, o1 = o_acc[nf][1] * inv_lo;
        float o2 = o_acc[nf][2] * inv_hi, o3 = o_acc[nf][3] * inv_hi;
        uint32_t h0 = pack_h2f(o0, o1), L0 = pack_resid(h0, o0, o1);
        uint32_t h1 = pack_h2f(o2, o3), L1 = pack_resid(h1, o2, o3);
        *(uint32_t*)(Oh + (size_t)row_lo_g * D_MODEL + col) = h0;
        *(uint32_t*)(Ol + (size_t)row_lo_g * D_MODEL + col) = L0;
        *(uint32_t*)(Oh + (size_t)row_hi_g * D_MODEL + col) = h1;
        *(uint32_t*)(Ol + (size_t)row_hi_g * D_MODEL + col) = L1;
    }
}

// ---------------------------------------------------------------------------
// Launch
// ---------------------------------------------------------------------------
extern "C" void kernel_launch(void* const* d_in, const int* in_sizes, int n_in,
                              void* d_out, int out_size) {
    const float* x  = (const float*)d_in[0];
    const float* fc = (const float*)d_in[1];
    const float* fs = (const float*)d_in[2];
    const float* wq = (const float*)d_in[4];
    const float* wk = (const float*)d_in[5];
    const float* wv = (const float*)d_in[6];
    const float* wo = (const float*)d_in[7];
    float* out = (float*)d_out;

    __half *xh, *xl, *qh, *ql, *kh, *kl, *vh, *vl, *aoh, *aol;
    __half *wqh, *wql, *wkh, *wkl, *wvh, *wvl, *woh, *wol;
    cudaGetSymbolAddress((void**)&xh,  g_xh);
    cudaGetSymbolAddress((void**)&xl,  g_xl);
    cudaGetSymbolAddress((void**)&qh,  g_qh);
    cudaGetSymbolAddress((void**)&ql,  g_ql);
    cudaGetSymbolAddress((void**)&kh,  g_kh);
    cudaGetSymbolAddress((void**)&kl,  g_kl);
    cudaGetSymbolAddress((void**)&vh,  g_vh);
    cudaGetSymbolAddress((void**)&vl,  g_vl);
    cudaGetSymbolAddress((void**)&aoh, g_aoh);
    cudaGetSymbolAddress((void**)&aol, g_aol);
    cudaGetSymbolAddress((void**)&wqh, g_wqh);
    cudaGetSymbolAddress((void**)&wql, g_wql);
    cudaGetSymbolAddress((void**)&wkh, g_wkh);
    cudaGetSymbolAddress((void**)&wkl, g_wkl);
    cudaGetSymbolAddress((void**)&wvh, g_wvh);
    cudaGetSymbolAddress((void**)&wvl, g_wvl);
    cudaGetSymbolAddress((void**)&woh, g_woh);
    cudaGetSymbolAddress((void**)&wol, g_wol);

    cudaFuncSetAttribute(qkv_gemm, cudaFuncAttributeMaxDynamicSharedMemorySize, G_SMEM);
    cudaFuncSetAttribute(wo_gemm,  cudaFuncAttributeMaxDynamicSharedMemorySize, G_SMEM);
    cudaFuncSetAttribute(flash_hmma, cudaFuncAttributeMaxDynamicSharedMemorySize, FSMEM);

    // Conversions (2 launches)
    split_kernel<<<(S_LEN * D_MODEL + 255) / 256, 256>>>(x, xh, xl, S_LEN * D_MODEL);
    transpose_split_all<<<dim3(D_MODEL / 32, D_MODEL / 32, 4), dim3(32, 8)>>>(
        wq, wk, wv, wo, wqh, wql, wkh, wkl, wvh, wvl, woh, wol);

    // Fused QKV projection (one launch, 768 CTAs)
    qkv_gemm<<<dim3(48, S_LEN / 128), 256, G_SMEM>>>(
        xh, xl, fc, fs, wqh, wql, wkh, wkl, wvh, wvl,
        qh, ql, kh, kl, vh, vl);

    // HMMA flash attention
    flash_hmma<<<dim3(S_LEN / 128, N_HEADS), 256, FSMEM>>>(
        qh, ql, kh, kl, vh, vl, aoh, aol);

    // Output projection
    wo_gemm<<<dim3(D_MODEL / 128, S_LEN / 128), 256, G_SMEM>>>(
        aoh, aol, woh, wol, out);
}

// round 6
// speedup vs baseline: 3.1773x; 1.0083x over previous
#include <cuda_runtime.h>
#include <cuda_fp16.h>
#include <cstdint>

// Problem constants
#define S_LEN 2048
#define D_MODEL 4096
#define N_HEADS 32
#define N_KV 8
#define HEAD_DIM 128
#define KVDIM (N_KV * HEAD_DIM)   // 1024

#define WSCALE 64.0f
#define INV_WSCALE (1.0f / 64.0f)
#define QK_SCALE 0.08838834764831845f  // 1/sqrt(128)

// ---------------------------------------------------------------------------
// Scratch (device globals)
// ---------------------------------------------------------------------------
__device__ __align__(128) __half g_xh[S_LEN * D_MODEL];
__device__ __align__(128) __half g_xl[S_LEN * D_MODEL];
__device__ __align__(128) __half g_qh[S_LEN * D_MODEL];
__device__ __align__(128) __half g_ql[S_LEN * D_MODEL];
__device__ __align__(128) __half g_kh[S_LEN * KVDIM];
__device__ __align__(128) __half g_kl[S_LEN * KVDIM];
__device__ __align__(128) __half g_vh[S_LEN * KVDIM];
__device__ __align__(128) __half g_vl[S_LEN * KVDIM];
__device__ __align__(128) __half g_aoh[S_LEN * D_MODEL];
__device__ __align__(128) __half g_aol[S_LEN * D_MODEL];
__device__ __align__(128) __half g_wqh[D_MODEL * D_MODEL];  // [N,K], x64
__device__ __align__(128) __half g_wql[D_MODEL * D_MODEL];
__device__ __align__(128) __half g_wkh[KVDIM * D_MODEL];
__device__ __align__(128) __half g_wkl[KVDIM * D_MODEL];
__device__ __align__(128) __half g_wvh[KVDIM * D_MODEL];
__device__ __align__(128) __half g_wvl[KVDIM * D_MODEL];
__device__ __align__(128) __half g_woh[D_MODEL * D_MODEL];
__device__ __align__(128) __half g_wol[D_MODEL * D_MODEL];

// ---------------------------------------------------------------------------
// Helpers
// ---------------------------------------------------------------------------
__device__ __forceinline__ uint32_t smem_u32(const void* p) {
    uint32_t a;
    asm("{ .reg .u64 t; cvta.to.shared.u64 t, %1; cvt.u32.u64 %0, t; }"
        : "=r"(a) : "l"(p));
    return a;
}
__device__ __forceinline__ uint32_t pack_h2f(float a, float b) {
    __half2 h = __floats2half2_rn(a, b);
    return *reinterpret_cast<uint32_t*>(&h);
}
__device__ __forceinline__ uint32_t pack_resid(uint32_t h, float a, float b) {
    __half2 hh = *reinterpret_cast<__half2*>(&h);
    float2 f = __half22float2(hh);
    return pack_h2f(a - f.x, b - f.y);
}
__device__ __forceinline__ float2 h2f2(uint32_t u) {
    __half2 hh = *reinterpret_cast<__half2*>(&u);
    return __half22float2(hh);
}

#define LDSM4(r0, r1, r2, r3, addr)                                           \
    asm volatile("ldmatrix.sync.aligned.m8n8.x4.shared.b16 {%0,%1,%2,%3}, [%4];" \
                 : "=r"(r0), "=r"(r1), "=r"(r2), "=r"(r3) : "r"(addr))
#define LDSM4T(r0, r1, r2, r3, addr)                                          \
    asm volatile("ldmatrix.sync.aligned.m8n8.x4.trans.shared.b16 {%0,%1,%2,%3}, [%4];" \
                 : "=r"(r0), "=r"(r1), "=r"(r2), "=r"(r3) : "r"(addr))
// fp32-accumulate MMA (hi pass)
#define MMA16816(d, a, b)                                                     \
    asm volatile(                                                             \
        "mma.sync.aligned.m16n8k16.row.col.f32.f16.f16.f32 "                  \
        "{%0,%1,%2,%3}, {%4,%5,%6,%7}, {%8,%9}, {%0,%1,%2,%3};"               \
        : "+f"((d)[0]), "+f"((d)[1]), "+f"((d)[2]), "+f"((d)[3])              \
        : "r"((a)[0]), "r"((a)[1]), "r"((a)[2]), "r"((a)[3]),                 \
          "r"((b)[0]), "r"((b)[1]))
// fp16-accumulate MMA (residual passes; d = 2x f16x2 regs)
#define MMA16816H(d, a, b)                                                    \
    asm volatile(                                                             \
        "mma.sync.aligned.m16n8k16.row.col.f16.f16.f16.f16 "                  \
        "{%0,%1}, {%2,%3,%4,%5}, {%6,%7}, {%0,%1};"                           \
        : "+r"((d)[0]), "+r"((d)[1])                                          \
        : "r"((a)[0]), "r"((a)[1]), "r"((a)[2]), "r"((a)[3]),                 \
          "r"((b)[0]), "r"((b)[1]))
#define CP16(s, g)                                                            \
    asm volatile("cp.async.cg.shared.global [%0], [%1], 16;"                  \
                 :: "r"(s), "l"(g) : "memory")

// ---------------------------------------------------------------------------
// HMMA GEMM with fp16 hi/lo split; residual passes in fp16 accumulate.
// Epilogue modes: 0 = fp32 out, 1 = rope+scale+split out, 2 = split out.
// ---------------------------------------------------------------------------
#define G_ROWB 144
#define G_TILEB (128 * G_ROWB)
#define G_STAGE (4 * G_TILEB)
#define G_SMEM (2 * G_STAGE)

struct GemmArgs {
    const __half *Ah, *Al, *Bh, *Bl;
    float* Cf;
    __half *Ch, *Cl;
    const float *fc, *fs;
    int N;
    float cscale, oscale;
    int mode;
};

__device__ __forceinline__ void gemm_body(const GemmArgs& ga, int m0, int n0,
                                          int K, char* smem) {
    const uint32_t sb = smem_u32(smem);
    const int tid = threadIdx.x;
    const int lane = tid & 31;
    const int wid = tid >> 5;
    const int wm = wid & 3;
    const int wn = wid >> 2;

    uint32_t s_off[4];
    size_t g_off[4];
#pragma unroll
    for (int it = 0; it < 4; it++) {
        int idx = it * 256 + tid;
        int r = idx >> 3;
        int c = idx & 7;
        s_off[it] = (uint32_t)(r * G_ROWB + c * 16);
        g_off[it] = (size_t)r * K + c * 8;
    }
    const __half* src[4] = {ga.Ah + (size_t)m0 * K, ga.Al + (size_t)m0 * K,
                            ga.Bh + (size_t)n0 * K, ga.Bl + (size_t)n0 * K};

    auto issue = [&](int i) {
        const uint32_t sbase = sb + (i & 1) * G_STAGE;
        const int k0 = i << 6;
#pragma unroll
        for (int t4 = 0; t4 < 4; t4++) {
            const __half* g = src[t4] + k0;
            const uint32_t st = sbase + t4 * G_TILEB;
#pragma unroll
            for (int it = 0; it < 4; it++) CP16(st + s_off[it], g + g_off[it]);
        }
        asm volatile("cp.async.commit_group;" ::: "memory");
    };

    uint32_t aoff[2], boff[4];
#pragma unroll
    for (int mt = 0; mt < 2; mt++) {
        int row = wm * 32 + mt * 16 + (lane & 15);
        aoff[mt] = (uint32_t)(row * G_ROWB + (lane >> 4) * 16);
    }
#pragma unroll
    for (int ng = 0; ng < 4; ng++) {
        int row = wn * 64 + ng * 16 + (lane & 15);
        boff[ng] = (uint32_t)(2 * G_TILEB + row * G_ROWB + (lane >> 4) * 16);
    }

    float acc[2][8][4];
    uint32_t acc16[2][8][2];
#pragma unroll
    for (int mt = 0; mt < 2; mt++)
#pragma unroll
        for (int n = 0; n < 8; n++) {
#pragma unroll
            for (int e = 0; e < 4; e++) acc[mt][n][e] = 0.f;
            acc16[mt][n][0] = 0u;
            acc16[mt][n][1] = 0u;
        }

    const int niter = K >> 6;
    issue(0);

    for (int i = 0; i < niter; i++) {
        asm volatile("cp.async.wait_group 0;" ::: "memory");
        __syncthreads();
        if (i + 1 < niter) issue(i + 1);

        const uint32_t st = sb + (i & 1) * G_STAGE;
#pragma unroll
        for (int ks = 0; ks < 4; ks++) {
            const uint32_t kadd = ks * 32;
            uint32_t ah[2][4], al[2][4], bh[8][2], bl[8][2];
#pragma unroll
            for (int mt = 0; mt < 2; mt++) {
                LDSM4(ah[mt][0], ah[mt][1], ah[mt][2], ah[mt][3],
                      st + aoff[mt] + kadd);
                LDSM4(al[mt][0], al[mt][1], al[mt][2], al[mt][3],
                      st + G_TILEB + aoff[mt] + kadd);
            }
#pragma unroll
            for (int ng = 0; ng < 4; ng++) {
                uint32_t r0, r1, r2, r3;
                LDSM4(r0, r1, r2, r3, st + boff[ng] + kadd);
                bh[ng * 2][0] = r0; bh[ng * 2][1] = r2;
                bh[ng * 2 + 1][0] = r1; bh[ng * 2 + 1][1] = r3;
                LDSM4(r0, r1, r2, r3, st + G_TILEB + boff[ng] + kadd);
                bl[ng * 2][0] = r0; bl[ng * 2][1] = r2;
                bl[ng * 2 + 1][0] = r1; bl[ng * 2 + 1][1] = r3;
            }
#pragma unroll
            for (int mt = 0; mt < 2; mt++)
#pragma unroll
                for (int n = 0; n < 8; n++) {
                    MMA16816(acc[mt][n], ah[mt], bh[n]);
                    MMA16816H(acc16[mt][n], al[mt], bh[n]);
                    MMA16816H(acc16[mt][n], ah[mt], bl[n]);
                }
        }
    }

    const int N = ga.N;
    const int row_b = m0 + wm * 32 + (lane >> 2);
    const int col_b = n0 + wn * 64 + (lane & 3) * 2;

#pragma unroll
    for (int mt = 0; mt < 2; mt++)
#pragma unroll
        for (int n = 0; n < 8; n++) {
            const int col = col_b + n * 8;
            const int r0_ = row_b + mt * 16;
            const int r1_ = r0_ + 8;
            float2 rlo = h2f2(acc16[mt][n][0]);
            float2 rhi = h2f2(acc16[mt][n][1]);
            float v0 = acc[mt][n][0] + rlo.x;
            float v1 = acc[mt][n][1] + rlo.y;
            float v2 = acc[mt][n][2] + rhi.x;
            float v3 = acc[mt][n][3] + rhi.y;
            if (ga.mode == 0) {
                float* c0 = ga.Cf + (size_t)r0_ * N + col;
                float* c1 = ga.Cf + (size_t)r1_ * N + col;
                c0[0] = v0 * ga.cscale;
                c0[1] = v1 * ga.cscale;
                c1[0] = v2 * ga.cscale;
                c1[1] = v3 * ga.cscale;
            } else {
                float x0 = v0 * ga.cscale, y0 = v1 * ga.cscale;
                float x1 = v2 * ga.cscale, y1 = v3 * ga.cscale;
                if (ga.mode == 1) {
                    int p = (col & 127) >> 1;
                    float c0v = ga.fc[r0_ * 64 + p], s0v = ga.fs[r0_ * 64 + p];
                    float c1v = ga.fc[r1_ * 64 + p], s1v = ga.fs[r1_ * 64 + p];
                    float nx0 = (x0 * c0v - y0 * s0v) * ga.oscale;
                    float ny0 = (x0 * s0v + y0 * c0v) * ga.oscale;
                    float nx1 = (x1 * c1v - y1 * s1v) * ga.oscale;
                    float ny1 = (x1 * s1v + y1 * c1v) * ga.oscale;
                    x0 = nx0; y0 = ny0; x1 = nx1; y1 = ny1;
                }
                uint32_t h0 = pack_h2f(x0, y0), l0 = pack_resid(h0, x0, y0);
                uint32_t h1 = pack_h2f(x1, y1), l1 = pack_resid(h1, x1, y1);
                *(uint32_t*)(ga.Ch + (size_t)r0_ * N + col) = h0;
                *(uint32_t*)(ga.Cl + (size_t)r0_ * N + col) = l0;
                *(uint32_t*)(ga.Ch + (size_t)r1_ * N + col) = h1;
                *(uint32_t*)(ga.Cl + (size_t)r1_ * N + col) = l1;
            }
        }
}

// Fused QKV projection
__global__ void __launch_bounds__(256, 1)
qkv_gemm(const __half* __restrict__ xh, const __half* __restrict__ xl,
         const float* __restrict__ fc, const float* __restrict__ fs,
         const __half* __restrict__ wqh, const __half* __restrict__ wql,
         const __half* __restrict__ wkh, const __half* __restrict__ wkl,
         const __half* __restrict__ wvh, const __half* __restrict__ wvl,
         __half* __restrict__ qh, __half* __restrict__ ql,
         __half* __restrict__ kh, __half* __restrict__ kl,
         __half* __restrict__ vh, __half* __restrict__ vl) {
    extern __shared__ char smem[];
    const int bx = blockIdx.x;
    GemmArgs ga;
    ga.Ah = xh; ga.Al = xl;
    ga.fc = fc; ga.fs = fs;
    ga.Cf = nullptr;
    ga.cscale = INV_WSCALE;
    int n0;
    if (bx < 32) {
        ga.Bh = wqh; ga.Bl = wql; ga.Ch = qh; ga.Cl = ql;
        ga.N = D_MODEL; ga.mode = 1; ga.oscale = QK_SCALE;
        n0 = bx * 128;
    } else if (bx < 40) {
        ga.Bh = wkh; ga.Bl = wkl; ga.Ch = kh; ga.Cl = kl;
        ga.N = KVDIM; ga.mode = 1; ga.oscale = 1.0f;
        n0 = (bx - 32) * 128;
    } else {
        ga.Bh = wvh; ga.Bl = wvl; ga.Ch = vh; ga.Cl = vl;
        ga.N = KVDIM; ga.mode = 2; ga.oscale = 1.0f;
        n0 = (bx - 40) * 128;
    }
    gemm_body(ga, blockIdx.y * 128, n0, D_MODEL, smem);
}

// Output projection (fp32 out)
__global__ void __launch_bounds__(256, 1)
wo_gemm(const __half* __restrict__ aoh, const __half* __restrict__ aol,
        const __half* __restrict__ woh, const __half* __restrict__ wol,
        float* __restrict__ out) {
    extern __shared__ char smem[];
    GemmArgs ga;
    ga.Ah = aoh; ga.Al = aol; ga.Bh = woh; ga.Bl = wol;
    ga.Cf = out; ga.Ch = nullptr; ga.Cl = nullptr;
    ga.fc = nullptr; ga.fs = nullptr;
    ga.N = D_MODEL; ga.cscale = INV_WSCALE; ga.oscale = 1.0f; ga.mode = 0;
    gemm_body(ga, blockIdx.y * 128, blockIdx.x * 128, D_MODEL, smem);
}

// ---------------------------------------------------------------------------
// Conversions
// ---------------------------------------------------------------------------
__global__ void split_kernel(const float* __restrict__ in,
                             __half* __restrict__ hi, __half* __restrict__ lo,
                             int n) {
    int i = blockIdx.x * blockDim.x + threadIdx.x;
    if (i >= n) return;
    float v = in[i];
    __half h = __float2half_rn(v);
    hi[i] = h;
    lo[i] = __float2half_rn(v - __half2float(h));
}

__global__ void __launch_bounds__(256) transpose_split_all(
    const float* __restrict__ wq, const float* __restrict__ wk,
    const float* __restrict__ wv, const float* __restrict__ wo,
    __half* __restrict__ wqh, __half* __restrict__ wql,
    __half* __restrict__ wkh, __half* __restrict__ wkl,
    __half* __restrict__ wvh, __half* __restrict__ wvl,
    __half* __restrict__ woh, __half* __restrict__ wol) {
    const int z = blockIdx.z;
    const float* W;
    __half *hi, *lo;
    int N;
    if (z == 0)      { W = wq; hi = wqh; lo = wql; N = D_MODEL; }
    else if (z == 1) { W = wk; hi = wkh; lo = wkl; N = KVDIM; }
    else if (z == 2) { W = wv; hi = wvh; lo = wvl; N = KVDIM; }
    else             { W = wo; hi = woh; lo = wol; N = D_MODEL; }
    const int n0 = blockIdx.x * 32;
    if (n0 >= N) return;
    const int k0 = blockIdx.y * 32;
    const int K = D_MODEL;

    __shared__ float t[32][33];
    const int tx = threadIdx.x;
#pragma unroll
    for (int j = threadIdx.y; j < 32; j += 8)
        t[j][tx] = W[(size_t)(k0 + j) * N + n0 + tx];
    __syncthreads();
#pragma unroll
    for (int j = threadIdx.y; j < 32; j += 8) {
        float v = t[tx][j] * WSCALE;
        __half h = __float2half_rn(v);
        size_t o = (size_t)(n0 + j) * K + k0 + tx;
        hi[o] = h;
        lo[o] = __float2half_rn(v - __half2float(h));
    }
}

// ---------------------------------------------------------------------------
// HMMA flash attention; residual MMAs in fp16 accumulate.
// ---------------------------------------------------------------------------
#define FRSB 272
#define FQ_BYTES (128 * FRSB)
#define FKV_TILE (64 * FRSB)
#define FSTAGE (4 * FKV_TILE)
#define FSMEM (2 * FQ_BYTES + 2 * FSTAGE)

__global__ void __launch_bounds__(256, 1)
flash_hmma(const __half* __restrict__ Qh, const __half* __restrict__ Ql,
           const __half* __restrict__ Kh, const __half* __restrict__ Kl,
           const __half* __restrict__ Vh, const __half* __restrict__ Vl,
           __half* __restrict__ Oh, __half* __restrict__ Ol) {
    extern __shared__ char smf[];
    const uint32_t sb = smem_u32(smf);
    const int tid = threadIdx.x, lane = tid & 31, w = tid >> 5;
    const int head = blockIdx.y, kvh = head >> 2;
    const int qt = gridDim.x - 1 - blockIdx.x;
    const int q0 = qt * 128;
    const int nt = (q0 >> 6) + 2;

#pragma unroll
    for (int it = 0; it < 8; it++) {
        int idx = it * 256 + tid;
        int r = idx >> 4, c = idx & 15;
        size_t go = (size_t)(q0 + r) * D_MODEL + head * HEAD_DIM + c * 8;
        uint32_t so = (uint32_t)(r * FRSB + c * 16);
        CP16(sb + so, Qh + go);
        CP16(sb + FQ_BYTES + so, Ql + go);
    }

    const __half* kvsrc[4] = {Kh, Kl, Vh, Vl};
    auto issue_kv = [&](int t) {
        const int k0 = t << 6;
        const uint32_t stage = sb + 2 * FQ_BYTES + (t & 1) * FSTAGE;
#pragma unroll
        for (int it = 0; it < 16; it++) {
            int idx = it * 256 + tid;
            int op = idx >> 10;
            int r = (idx >> 4) & 63, c = idx & 15;
            const __half* g = kvsrc[op] + (size_t)(k0 + r) * KVDIM +
                              kvh * HEAD_DIM + c * 8;
            CP16(stage + op * FKV_TILE + r * FRSB + c * 16, g);
        }
        asm volatile("cp.async.commit_group;" ::: "memory");
    };
    issue_kv(0);

    const uint32_t qa_h = sb + (w * 16 + (lane & 15)) * FRSB + (lane >> 4) * 16;
    const uint32_t qa_l = qa_h + FQ_BYTES;
    const uint32_t kvoff = (uint32_t)((lane & 15) * FRSB + (lane >> 4) * 16);

    float m_lo = -1e30f, m_hi = -1e30f, l_lo = 0.f, l_hi = 0.f;
    float o_acc[16][4];
#pragma unroll
    for (int nf = 0; nf < 16; nf++)
#pragma unroll
        for (int e = 0; e < 4; e++) o_acc[nf][e] = 0.f;

    const int row_lo_g = q0 + w * 16 + (lane >> 2);
    const int row_hi_g = row_lo_g + 8;

    for (int t = 0; t < nt; t++) {
        asm volatile("cp.async.wait_group 0;" ::: "memory");
        __syncthreads();
        if (t + 1 < nt) issue_kv(t + 1);

        const uint32_t stage = sb + 2 * FQ_BYTES + (t & 1) * FSTAGE;
        const uint32_t kb = stage + kvoff;
        const uint32_t kbl = kb + FKV_TILE;
        const uint32_t vb = stage + 2 * FKV_TILE + kvoff;
        const uint32_t vbl = vb + FKV_TILE;
        const int k0 = t << 6;

        // ---- S = Q @ K^T: hi pass fp32 acc, residuals fp16 acc
        float sa32[8][4];
        uint32_t sa16[8][2];
#pragma unroll
        for (int nf = 0; nf < 8; nf++) {
#pragma unroll
            for (int e = 0; e < 4; e++) sa32[nf][e] = 0.f;
            sa16[nf][0] = 0u;
            sa16[nf][1] = 0u;
        }

#pragma unroll
        for (int ks = 0; ks < 8; ks++) {
            uint32_t ah[4], al[4];
            LDSM4(ah[0], ah[1], ah[2], ah[3], qa_h + ks * 32);
            LDSM4(al[0], al[1], al[2], al[3], qa_l + ks * 32);
#pragma unroll
            for (int ng = 0; ng < 4; ng++) {
                uint32_t h0, h1, h2, h3, l0, l1, l2, l3;
                LDSM4(h0, h1, h2, h3, kb + ng * (16 * FRSB) + ks * 32);
                LDSM4(l0, l1, l2, l3, kbl + ng * (16 * FRSB) + ks * 32);
                uint32_t bh0[2] = {h0, h2}, bh1[2] = {h1, h3};
                uint32_t bl0[2] = {l0, l2}, bl1[2] = {l1, l3};
                MMA16816(sa32[2 * ng], ah, bh0);
                MMA16816H(sa16[2 * ng], al, bh0);
                MMA16816H(sa16[2 * ng], ah, bl0);
                MMA16816(sa32[2 * ng + 1], ah, bh1);
                MMA16816H(sa16[2 * ng + 1], al, bh1);
                MMA16816H(sa16[2 * ng + 1], ah, bl1);
            }
        }

        // merge residuals
        float sa[8][4];
#pragma unroll
        for (int nf = 0; nf < 8; nf++) {
            float2 rlo = h2f2(sa16[nf][0]);
            float2 rhi = h2f2(sa16[nf][1]);
            sa[nf][0] = sa32[nf][0] + rlo.x;
            sa[nf][1] = sa32[nf][1] + rlo.y;
            sa[nf][2] = sa32[nf][2] + rhi.x;
            sa[nf][3] = sa32[nf][3] + rhi.y;
        }

        if (t >= nt - 2) {
#pragma unroll
            for (int nf = 0; nf < 8; nf++) {
                int cb = k0 + nf * 8 + (lane & 3) * 2;
                if (cb > row_lo_g) sa[nf][0] = -1e30f;
                if (cb + 1 > row_lo_g) sa[nf][1] = -1e30f;
                if (cb > row_hi_g) sa[nf][2] = -1e30f;
                if (cb + 1 > row_hi_g) sa[nf][3] = -1e30f;
            }
        }

        float tm_lo = -1e30f, tm_hi = -1e30f;
#pragma unroll
        for (int nf = 0; nf < 8; nf++) {
            tm_lo = fmaxf(tm_lo, fmaxf(sa[nf][0], sa[nf][1]));
            tm_hi = fmaxf(tm_hi, fmaxf(sa[nf][2], sa[nf][3]));
        }
        tm_lo = fmaxf(tm_lo, __shfl_xor_sync(0xffffffffu, tm_lo, 1));
        tm_lo = fmaxf(tm_lo, __shfl_xor_sync(0xffffffffu, tm_lo, 2));
        tm_hi = fmaxf(tm_hi, __shfl_xor_sync(0xffffffffu, tm_hi, 1));
        tm_hi = fmaxf(tm_hi, __shfl_xor_sync(0xffffffffu, tm_hi, 2));

        float mn_lo = fmaxf(m_lo, tm_lo), mn_hi = fmaxf(m_hi, tm_hi);
        float al_lo = __expf(m_lo - mn_lo), al_hi = __expf(m_hi - mn_hi);
        m_lo = mn_lo; m_hi = mn_hi;

        float sum_lo = 0.f, sum_hi = 0.f;
#pragma unroll
        for (int nf = 0; nf < 8; nf++) {
            sa[nf][0] = __expf(sa[nf][0] - mn_lo);
            sa[nf][1] = __expf(sa[nf][1] - mn_lo);
            sa[nf][2] = __expf(sa[nf][2] - mn_hi);
            sa[nf][3] = __expf(sa[nf][3] - mn_hi);
            sum_lo += sa[nf][0] + sa[nf][1];
            sum_hi += sa[nf][2] + sa[nf][3];
        }
        sum_lo += __shfl_xor_sync(0xffffffffu, sum_lo, 1);
        sum_lo += __shfl_xor_sync(0xffffffffu, sum_lo, 2);
        sum_hi += __shfl_xor_sync(0xffffffffu, sum_hi, 1);
        sum_hi += __shfl_xor_sync(0xffffffffu, sum_hi, 2);
        l_lo = l_lo * al_lo + sum_lo;
        l_hi = l_hi * al_hi + sum_hi;

#pragma unroll
        for (int nf = 0; nf < 16; nf++) {
            o_acc[nf][0] *= al_lo; o_acc[nf][1] *= al_lo;
            o_acc[nf][2] *= al_hi; o_acc[nf][3] *= al_hi;
        }

        uint32_t pah[4][4], pal[4][4];
#pragma unroll
        for (int j = 0; j < 4; j++) {
            pah[j][0] = pack_h2f(sa[2 * j][0], sa[2 * j][1]);
            pal[j][0] = pack_resid(pah[j][0], sa[2 * j][0], sa[2 * j][1]);
            pah[j][1] = pack_h2f(sa[2 * j][2], sa[2 * j][3]);
            pal[j][1] = pack_resid(pah[j][1], sa[2 * j][2], sa[2 * j][3]);
            pah[j][2] = pack_h2f(sa[2 * j + 1][0], sa[2 * j + 1][1]);
            pal[j][2] = pack_resid(pah[j][2], sa[2 * j + 1][0], sa[2 * j + 1][1]);
            pah[j][3] = pack_h2f(sa[2 * j + 1][2], sa[2 * j + 1][3]);
            pal[j][3] = pack_resid(pah[j][3], sa[2 * j + 1][2], sa[2 * j + 1][3]);
        }

        // ---- O += P @ V: hi pass fp32, residuals fp16 (per-tile, promoted)
        uint32_t o16[16][2];
#pragma unroll
        for (int nf = 0; nf < 16; nf++) { o16[nf][0] = 0u; o16[nf][1] = 0u; }

#pragma unroll
        for (int j = 0; j < 4; j++) {
#pragma unroll
            for (int dg = 0; dg < 8; dg++) {
                uint32_t h0, h1, h2, h3, l0, l1, l2, l3;
                LDSM4T(h0, h1, h2, h3, vb + j * (16 * FRSB) + dg * 32);
                LDSM4T(l0, l1, l2, l3, vbl + j * (16 * FRSB) + dg * 32);
                uint32_t bh0[2] = {h0, h1}, bh1[2] = {h2, h3};
                uint32_t bl0[2] = {l0, l1}, bl1[2] = {l2, l3};
                MMA16816(o_acc[2 * dg], pah[j], bh0);
                MMA16816H(o16[2 * dg], pal[j], bh0);
                MMA16816H(o16[2 * dg], pah[j], bl0);
                MMA16816(o_acc[2 * dg + 1], pah[j], bh1);
                MMA16816H(o16[2 * dg + 1], pal[j], bh1);
                MMA16816H(o16[2 * dg + 1], pah[j], bl1);
            }
        }
#pragma unroll
        for (int nf = 0; nf < 16; nf++) {
            float2 rlo = h2f2(o16[nf][0]);
            float2 rhi = h2f2(o16[nf][1]);
            o_acc[nf][0] += rlo.x;
            o_acc[nf][1] += rlo.y;
            o_acc[nf][2] += rhi.x;
            o_acc[nf][3] += rhi.y;
        }
    }

    const float inv_lo = 1.f / l_lo, inv_hi = 1.f / l_hi;
#pragma unroll
    for (int nf = 0; nf < 16; nf++) {
        int col = head * HEAD_DIM + nf * 8 + (lane & 3) * 2;
        float o0 = o_acc[nf][0] * inv_lo, o1 = o_acc[nf][1] * inv_lo;
        float o2 = o_acc[nf][2] * inv_hi, o3 = o_acc[nf][3] * inv_hi;
        uint32_t h0 = pack_h2f(o0, o1), L0 = pack_resid(h0, o0, o1);
        uint32_t h1 = pack_h2f(o2, o3), L1 = pack_resid(h1, o2, o3);
        *(uint32_t*)(Oh + (size_t)row_lo_g * D_MODEL + col) = h0;
        *(uint32_t*)(Ol + (size_t)row_lo_g * D_MODEL + col) = L0;
        *(uint32_t*)(Oh + (size_t)row_hi_g * D_MODEL + col) = h1;
        *(uint32_t*)(Ol + (size_t)row_hi_g * D_MODEL + col) = L1;
    }
}

// ---------------------------------------------------------------------------
// Launch
// ---------------------------------------------------------------------------
extern "C" void kernel_launch(void* const* d_in, const int* in_sizes, int n_in,
                              void* d_out, int out_size) {
    const float* x  = (const float*)d_in[0];
    const float* fc = (const float*)d_in[1];
    const float* fs = (const float*)d_in[2];
    const float* wq = (const float*)d_in[4];
    const float* wk = (const float*)d_in[5];
    const float* wv = (const float*)d_in[6];
    const float* wo = (const float*)d_in[7];
    float* out = (float*)d_out;

    __half *xh, *xl, *qh, *ql, *kh, *kl, *vh, *vl, *aoh, *aol;
    __half *wqh, *wql, *wkh, *wkl, *wvh, *wvl, *woh, *wol;
    cudaGetSymbolAddress((void**)&xh,  g_xh);
    cudaGetSymbolAddress((void**)&xl,  g_xl);
    cudaGetSymbolAddress((void**)&qh,  g_qh);
    cudaGetSymbolAddress((void**)&ql,  g_ql);
    cudaGetSymbolAddress((void**)&kh,  g_kh);
    cudaGetSymbolAddress((void**)&kl,  g_kl);
    cudaGetSymbolAddress((void**)&vh,  g_vh);
    cudaGetSymbolAddress((void**)&vl,  g_vl);
    cudaGetSymbolAddress((void**)&aoh, g_aoh);
    cudaGetSymbolAddress((void**)&aol, g_aol);
    cudaGetSymbolAddress((void**)&wqh, g_wqh);
    cudaGetSymbolAddress((void**)&wql, g_wql);
    cudaGetSymbolAddress((void**)&wkh, g_wkh);
    cudaGetSymbolAddress((void**)&wkl, g_wkl);
    cudaGetSymbolAddress((void**)&wvh, g_wvh);
    cudaGetSymbolAddress((void**)&wvl, g_wvl);
    cudaGetSymbolAddress((void**)&woh, g_woh);
    cudaGetSymbolAddress((void**)&wol, g_wol);

    cudaFuncSetAttribute(qkv_gemm, cudaFuncAttributeMaxDynamicSharedMemorySize, G_SMEM);
    cudaFuncSetAttribute(wo_gemm,  cudaFuncAttributeMaxDynamicSharedMemorySize, G_SMEM);
    cudaFuncSetAttribute(flash_hmma, cudaFuncAttributeMaxDynamicSharedMemorySize, FSMEM);

    split_kernel<<<(S_LEN * D_MODEL + 255) / 256, 256>>>(x, xh, xl, S_LEN * D_MODEL);
    transpose_split_all<<<dim3(D_MODEL / 32, D_MODEL / 32, 4), dim3(32, 8)>>>(
        wq, wk, wv, wo, wqh, wql, wkh, wkl, wvh, wvl, woh, wol);

    qkv_gemm<<<dim3(48, S_LEN / 128), 256, G_SMEM>>>(
        xh, xl, fc, fs, wqh, wql, wkh, wkl, wvh, wvl,
        qh, ql, kh, kl, vh, vl);

    flash_hmma<<<dim3(S_LEN / 128, N_HEADS), 256, FSMEM>>>(
        qh, ql, kh, kl, vh, vl, aoh, aol);

    wo_gemm<<<dim3(D_MODEL / 128, S_LEN / 128), 256, G_SMEM>>>(
        aoh, aol, woh, wol, out);
}

// round 9
// speedup vs baseline: 3.2152x; 1.0119x over previous
#include <cuda_runtime.h>
#include <cuda_fp16.h>
#include <cstdint>

// Problem constants
#define S_LEN 2048
#define D_MODEL 4096
#define N_HEADS 32
#define N_KV 8
#define HEAD_DIM 128
#define KVDIM (N_KV * HEAD_DIM)   // 1024

#define WSCALE 64.0f
#define INV_WSCALE (1.0f / 64.0f)
#define QK_SCALE 0.08838834764831845f  // 1/sqrt(128)

// ---------------------------------------------------------------------------
// Scratch (device globals)
// ---------------------------------------------------------------------------
__device__ __align__(128) __half g_xh[S_LEN * D_MODEL];
__device__ __align__(128) __half g_xl[S_LEN * D_MODEL];
__device__ __align__(128) __half g_qh[S_LEN * D_MODEL];
__device__ __align__(128) __half g_ql[S_LEN * D_MODEL];
__device__ __align__(128) __half g_kh[S_LEN * KVDIM];
__device__ __align__(128) __half g_kl[S_LEN * KVDIM];
__device__ __align__(128) __half g_vh[S_LEN * KVDIM];
__device__ __align__(128) __half g_vl[S_LEN * KVDIM];
__device__ __align__(128) __half g_aoh[S_LEN * D_MODEL];
__device__ __align__(128) __half g_aol[S_LEN * D_MODEL];
__device__ __align__(128) __half g_wqh[D_MODEL * D_MODEL];  // [N,K], x64
__device__ __align__(128) __half g_wql[D_MODEL * D_MODEL];
__device__ __align__(128) __half g_wkh[KVDIM * D_MODEL];
__device__ __align__(128) __half g_wkl[KVDIM * D_MODEL];
__device__ __align__(128) __half g_wvh[KVDIM * D_MODEL];
__device__ __align__(128) __half g_wvl[KVDIM * D_MODEL];
__device__ __align__(128) __half g_woh[D_MODEL * D_MODEL];
__device__ __align__(128) __half g_wol[D_MODEL * D_MODEL];

// ---------------------------------------------------------------------------
// Helpers
// ---------------------------------------------------------------------------
__device__ __forceinline__ uint32_t smem_u32(const void* p) {
    uint32_t a;
    asm("{ .reg .u64 t; cvta.to.shared.u64 t, %1; cvt.u32.u64 %0, t; }"
        : "=r"(a) : "l"(p));
    return a;
}
__device__ __forceinline__ uint32_t pack_h2f(float a, float b) {
    __half2 h = __floats2half2_rn(a, b);
    return *reinterpret_cast<uint32_t*>(&h);
}
__device__ __forceinline__ uint32_t pack_resid(uint32_t h, float a, float b) {
    __half2 hh = *reinterpret_cast<__half2*>(&h);
    float2 f = __half22float2(hh);
    return pack_h2f(a - f.x, b - f.y);
}
__device__ __forceinline__ float2 h2f2(uint32_t u) {
    __half2 hh = *reinterpret_cast<__half2*>(&u);
    return __half22float2(hh);
}

#define LDSM4(r0, r1, r2, r3, addr)                                           \
    asm volatile("ldmatrix.sync.aligned.m8n8.x4.shared.b16 {%0,%1,%2,%3}, [%4];" \
                 : "=r"(r0), "=r"(r1), "=r"(r2), "=r"(r3) : "r"(addr))
#define LDSM4T(r0, r1, r2, r3, addr)                                          \
    asm volatile("ldmatrix.sync.aligned.m8n8.x4.trans.shared.b16 {%0,%1,%2,%3}, [%4];" \
                 : "=r"(r0), "=r"(r1), "=r"(r2), "=r"(r3) : "r"(addr))
#define MMA16816(d, a, b)                                                     \
    asm volatile(                                                             \
        "mma.sync.aligned.m16n8k16.row.col.f32.f16.f16.f32 "                  \
        "{%0,%1,%2,%3}, {%4,%5,%6,%7}, {%8,%9}, {%0,%1,%2,%3};"               \
        : "+f"((d)[0]), "+f"((d)[1]), "+f"((d)[2]), "+f"((d)[3])              \
        : "r"((a)[0]), "r"((a)[1]), "r"((a)[2]), "r"((a)[3]),                 \
          "r"((b)[0]), "r"((b)[1]))
#define MMA16816H(d, a, b)                                                    \
    asm volatile(                                                             \
        "mma.sync.aligned.m16n8k16.row.col.f16.f16.f16.f16 "                  \
        "{%0,%1}, {%2,%3,%4,%5}, {%6,%7}, {%0,%1};"                           \
        : "+r"((d)[0]), "+r"((d)[1])                                          \
        : "r"((a)[0]), "r"((a)[1]), "r"((a)[2]), "r"((a)[3]),                 \
          "r"((b)[0]), "r"((b)[1]))
#define CP16(s, g)                                                            \
    asm volatile("cp.async.cg.shared.global [%0], [%1], 16;"                  \
                 :: "r"(s), "l"(g) : "memory")

// ---------------------------------------------------------------------------
// HMMA GEMM, fp16 hi/lo split, 512 threads (16 warps, 32x32 warp tiles).
// Pass-major MMA order to break accumulator dependency chains.
// ---------------------------------------------------------------------------
#define G_ROWB 144
#define G_TILEB (128 * G_ROWB)
#define G_STAGE (4 * G_TILEB)
#define G_SMEM (2 * G_STAGE)

struct GemmArgs {
    const __half *Ah, *Al, *Bh, *Bl;
    float* Cf;
    __half *Ch, *Cl;
    const float *fc, *fs;
    int N;
    float cscale, oscale;
    int mode;
};

__device__ __forceinline__ void gemm_body(const GemmArgs& ga, int m0, int n0,
                                          int K, char* smem) {
    const uint32_t sb = smem_u32(smem);
    const int tid = threadIdx.x;
    const int lane = tid & 31;
    const int wid = tid >> 5;
    const int wm = wid & 3;        // 4 warps along M (32 rows each)
    const int wn = wid >> 2;       // 4 warps along N (32 cols each)

    // Loader precompute: 2 cp.async per tile per thread (1024 int4 / 512 thr)
    uint32_t s_off[2];
    size_t g_off[2];
#pragma unroll
    for (int it = 0; it < 2; it++) {
        int idx = it * 512 + tid;
        int r = idx >> 3;
        int c = idx & 7;
        s_off[it] = (uint32_t)(r * G_ROWB + c * 16);
        g_off[it] = (size_t)r * K + c * 8;
    }
    const __half* src[4] = {ga.Ah + (size_t)m0 * K, ga.Al + (size_t)m0 * K,
                            ga.Bh + (size_t)n0 * K, ga.Bl + (size_t)n0 * K};

    auto issue = [&](int i) {
        const uint32_t sbase = sb + (i & 1) * G_STAGE;
        const int k0 = i << 6;
#pragma unroll
        for (int t4 = 0; t4 < 4; t4++) {
            const __half* g = src[t4] + k0;
            const uint32_t st = sbase + t4 * G_TILEB;
#pragma unroll
            for (int it = 0; it < 2; it++) CP16(st + s_off[it], g + g_off[it]);
        }
        asm volatile("cp.async.commit_group;" ::: "memory");
    };

    uint32_t aoff[2], boff[2];
#pragma unroll
    for (int mt = 0; mt < 2; mt++) {
        int row = wm * 32 + mt * 16 + (lane & 15);
        aoff[mt] = (uint32_t)(row * G_ROWB + (lane >> 4) * 16);
    }
#pragma unroll
    for (int ng = 0; ng < 2; ng++) {
        int row = wn * 32 + ng * 16 + (lane & 15);
        boff[ng] = (uint32_t)(2 * G_TILEB + row * G_ROWB + (lane >> 4) * 16);
    }

    float acc[2][4][4];
    uint32_t acc16[2][4][2];
#pragma unroll
    for (int mt = 0; mt < 2; mt++)
#pragma unroll
        for (int n = 0; n < 4; n++) {
#pragma unroll
            for (int e = 0; e < 4; e++) acc[mt][n][e] = 0.f;
            acc16[mt][n][0] = 0u;
            acc16[mt][n][1] = 0u;
        }

    const int niter = K >> 6;
    issue(0);

    for (int i = 0; i < niter; i++) {
        asm volatile("cp.async.wait_group 0;" ::: "memory");
        __syncthreads();
        if (i + 1 < niter) issue(i + 1);

        const uint32_t st = sb + (i & 1) * G_STAGE;
#pragma unroll
        for (int ks = 0; ks < 4; ks++) {
            const uint32_t kadd = ks * 32;
            uint32_t ah[2][4], al[2][4], bh[4][2], bl[4][2];
#pragma unroll
            for (int mt = 0; mt < 2; mt++) {
                LDSM4(ah[mt][0], ah[mt][1], ah[mt][2], ah[mt][3],
                      st + aoff[mt] + kadd);
                LDSM4(al[mt][0], al[mt][1], al[mt][2], al[mt][3],
                      st + G_TILEB + aoff[mt] + kadd);
            }
#pragma unroll
            for (int ng = 0; ng < 2; ng++) {
                uint32_t r0, r1, r2, r3;
                LDSM4(r0, r1, r2, r3, st + boff[ng] + kadd);
                bh[ng * 2][0] = r0; bh[ng * 2][1] = r2;
                bh[ng * 2 + 1][0] = r1; bh[ng * 2 + 1][1] = r3;
                LDSM4(r0, r1, r2, r3, st + G_TILEB + boff[ng] + kadd);
                bl[ng * 2][0] = r0; bl[ng * 2][1] = r2;
                bl[ng * 2 + 1][0] = r1; bl[ng * 2 + 1][1] = r3;
            }
            // Pass-major order: dependent acc16 MMAs are 8 instructions apart
#pragma unroll
            for (int mt = 0; mt < 2; mt++)
#pragma unroll
                for (int n = 0; n < 4; n++) MMA16816(acc[mt][n], ah[mt], bh[n]);
#pragma unroll
            for (int mt = 0; mt < 2; mt++)
#pragma unroll
                for (int n = 0; n < 4; n++) MMA16816H(acc16[mt][n], al[mt], bh[n]);
#pragma unroll
            for (int mt = 0; mt < 2; mt++)
#pragma unroll
                for (int n = 0; n < 4; n++) MMA16816H(acc16[mt][n], ah[mt], bl[n]);
        }
    }

    const int N = ga.N;
    const int row_b = m0 + wm * 32 + (lane >> 2);
    const int col_b = n0 + wn * 32 + (lane & 3) * 2;

#pragma unroll
    for (int mt = 0; mt < 2; mt++)
#pragma unroll
        for (int n = 0; n < 4; n++) {
            const int col = col_b + n * 8;
            const int r0_ = row_b + mt * 16;
            const int r1_ = r0_ + 8;
            float2 rlo = h2f2(acc16[mt][n][0]);
            float2 rhi = h2f2(acc16[mt][n][1]);
            float v0 = acc[mt][n][0] + rlo.x;
            float v1 = acc[mt][n][1] + rlo.y;
            float v2 = acc[mt][n][2] + rhi.x;
            float v3 = acc[mt][n][3] + rhi.y;
            if (ga.mode == 0) {
                float* c0 = ga.Cf + (size_t)r0_ * N + col;
                float* c1 = ga.Cf + (size_t)r1_ * N + col;
                c0[0] = v0 * ga.cscale;
                c0[1] = v1 * ga.cscale;
                c1[0] = v2 * ga.cscale;
                c1[1] = v3 * ga.cscale;
            } else {
                float x0 = v0 * ga.cscale, y0 = v1 * ga.cscale;
                float x1 = v2 * ga.cscale, y1 = v3 * ga.cscale;
                if (ga.mode == 1) {
                    int p = (col & 127) >> 1;
                    float c0v = ga.fc[r0_ * 64 + p], s0v = ga.fs[r0_ * 64 + p];
                    float c1v = ga.fc[r1_ * 64 + p], s1v = ga.fs[r1_ * 64 + p];
                    float nx0 = (x0 * c0v - y0 * s0v) * ga.oscale;
                    float ny0 = (x0 * s0v + y0 * c0v) * ga.oscale;
                    float nx1 = (x1 * c1v - y1 * s1v) * ga.oscale;
                    float ny1 = (x1 * s1v + y1 * c1v) * ga.oscale;
                    x0 = nx0; y0 = ny0; x1 = nx1; y1 = ny1;
                }
                uint32_t h0 = pack_h2f(x0, y0), l0 = pack_resid(h0, x0, y0);
                uint32_t h1 = pack_h2f(x1, y1), l1 = pack_resid(h1, x1, y1);
                *(uint32_t*)(ga.Ch + (size_t)r0_ * N + col) = h0;
                *(uint32_t*)(ga.Cl + (size_t)r0_ * N + col) = l0;
                *(uint32_t*)(ga.Ch + (size_t)r1_ * N + col) = h1;
                *(uint32_t*)(ga.Cl + (size_t)r1_ * N + col) = l1;
            }
        }
}

// Fused QKV projection (512 threads)
__global__ void __launch_bounds__(512, 1)
qkv_gemm(const __half* __restrict__ xh, const __half* __restrict__ xl,
         const float* __restrict__ fc, const float* __restrict__ fs,
         const __half* __restrict__ wqh, const __half* __restrict__ wql,
         const __half* __restrict__ wkh, const __half* __restrict__ wkl,
         const __half* __restrict__ wvh, const __half* __restrict__ wvl,
         __half* __restrict__ qh, __half* __restrict__ ql,
         __half* __restrict__ kh, __half* __restrict__ kl,
         __half* __restrict__ vh, __half* __restrict__ vl) {
    extern __shared__ char smem[];
    const int bx = blockIdx.x;
    GemmArgs ga;
    ga.Ah = xh; ga.Al = xl;
    ga.fc = fc; ga.fs = fs;
    ga.Cf = nullptr;
    ga.cscale = INV_WSCALE;
    int n0;
    if (bx < 32) {
        ga.Bh = wqh; ga.Bl = wql; ga.Ch = qh; ga.Cl = ql;
        ga.N = D_MODEL; ga.mode = 1; ga.oscale = QK_SCALE;
        n0 = bx * 128;
    } else if (bx < 40) {
        ga.Bh = wkh; ga.Bl = wkl; ga.Ch = kh; ga.Cl = kl;
        ga.N = KVDIM; ga.mode = 1; ga.oscale = 1.0f;
        n0 = (bx - 32) * 128;
    } else {
        ga.Bh = wvh; ga.Bl = wvl; ga.Ch = vh; ga.Cl = vl;
        ga.N = KVDIM; ga.mode = 2; ga.oscale = 1.0f;
        n0 = (bx - 40) * 128;
    }
    gemm_body(ga, blockIdx.y * 128, n0, D_MODEL, smem);
}

__global__ void __launch_bounds__(512, 1)
wo_gemm(const __half* __restrict__ aoh, const __half* __restrict__ aol,
        const __half* __restrict__ woh, const __half* __restrict__ wol,
        float* __restrict__ out) {
    extern __shared__ char smem[];
    GemmArgs ga;
    ga.Ah = aoh; ga.Al = aol; ga.Bh = woh; ga.Bl = wol;
    ga.Cf = out; ga.Ch = nullptr; ga.Cl = nullptr;
    ga.fc = nullptr; ga.fs = nullptr;
    ga.N = D_MODEL; ga.cscale = INV_WSCALE; ga.oscale = 1.0f; ga.mode = 0;
    gemm_body(ga, blockIdx.y * 128, blockIdx.x * 128, D_MODEL, smem);
}

// ---------------------------------------------------------------------------
// Conversions
// ---------------------------------------------------------------------------
__global__ void split_kernel(const float* __restrict__ in,
                             __half* __restrict__ hi, __half* __restrict__ lo,
                             int n) {
    int i = blockIdx.x * blockDim.x + threadIdx.x;
    if (i >= n) return;
    float v = in[i];
    __half h = __float2half_rn(v);
    hi[i] = h;
    lo[i] = __float2half_rn(v - __half2float(h));
}

__global__ void __launch_bounds__(256) transpose_split_all(
    const float* __restrict__ wq, const float* __restrict__ wk,
    const float* __restrict__ wv, const float* __restrict__ wo,
    __half* __restrict__ wqh, __half* __restrict__ wql,
    __half* __restrict__ wkh, __half* __restrict__ wkl,
    __half* __restrict__ wvh, __half* __restrict__ wvl,
    __half* __restrict__ woh, __half* __restrict__ wol) {
    const int z = blockIdx.z;
    const float* W;
    __half *hi, *lo;
    int N;
    if (z == 0)      { W = wq; hi = wqh; lo = wql; N = D_MODEL; }
    else if (z == 1) { W = wk; hi = wkh; lo = wkl; N = KVDIM; }
    else if (z == 2) { W = wv; hi = wvh; lo = wvl; N = KVDIM; }
    else             { W = wo; hi = woh; lo = wol; N = D_MODEL; }
    const int n0 = blockIdx.x * 32;
    if (n0 >= N) return;
    const int k0 = blockIdx.y * 32;
    const int K = D_MODEL;

    __shared__ float t[32][33];
    const int tx = threadIdx.x;
#pragma unroll
    for (int j = threadIdx.y; j < 32; j += 8)
        t[j][tx] = W[(size_t)(k0 + j) * N + n0 + tx];
    __syncthreads();
#pragma unroll
    for (int j = threadIdx.y; j < 32; j += 8) {
        float v = t[tx][j] * WSCALE;
        __half h = __float2half_rn(v);
        size_t o = (size_t)(n0 + j) * K + k0 + tx;
        hi[o] = h;
        lo[o] = __float2half_rn(v - __half2float(h));
    }
}

// ---------------------------------------------------------------------------
// HMMA flash attention (unchanged from round 6)
// ---------------------------------------------------------------------------
#define FRSB 272
#define FQ_BYTES (128 * FRSB)
#define FKV_TILE (64 * FRSB)
#define FSTAGE (4 * FKV_TILE)
#define FSMEM (2 * FQ_BYTES + 2 * FSTAGE)

__global__ void __launch_bounds__(256, 1)
flash_hmma(const __half* __restrict__ Qh, const __half* __restrict__ Ql,
           const __half* __restrict__ Kh, const __half* __restrict__ Kl,
           const __half* __restrict__ Vh, const __half* __restrict__ Vl,
           __half* __restrict__ Oh, __half* __restrict__ Ol) {
    extern __shared__ char smf[];
    const uint32_t sb = smem_u32(smf);
    const int tid = threadIdx.x, lane = tid & 31, w = tid >> 5;
    const int head = blockIdx.y, kvh = head >> 2;
    const int qt = gridDim.x - 1 - blockIdx.x;
    const int q0 = qt * 128;
    const int nt = (q0 >> 6) + 2;

#pragma unroll
    for (int it = 0; it < 8; it++) {
        int idx = it * 256 + tid;
        int r = idx >> 4, c = idx & 15;
        size_t go = (size_t)(q0 + r) * D_MODEL + head * HEAD_DIM + c * 8;
        uint32_t so = (uint32_t)(r * FRSB + c * 16);
        CP16(sb + so, Qh + go);
        CP16(sb + FQ_BYTES + so, Ql + go);
    }

    const __half* kvsrc[4] = {Kh, Kl, Vh, Vl};
    auto issue_kv = [&](int t) {
        const int k0 = t << 6;
        const uint32_t stage = sb + 2 * FQ_BYTES + (t & 1) * FSTAGE;
#pragma unroll
        for (int it = 0; it < 16; it++) {
            int idx = it * 256 + tid;
            int op = idx >> 10;
            int r = (idx >> 4) & 63, c = idx & 15;
            const __half* g = kvsrc[op] + (size_t)(k0 + r) * KVDIM +
                              kvh * HEAD_DIM + c * 8;
            CP16(stage + op * FKV_TILE + r * FRSB + c * 16, g);
        }
        asm volatile("cp.async.commit_group;" ::: "memory");
    };
    issue_kv(0);

    const uint32_t qa_h = sb + (w * 16 + (lane & 15)) * FRSB + (lane >> 4) * 16;
    const uint32_t qa_l = qa_h + FQ_BYTES;
    const uint32_t kvoff = (uint32_t)((lane & 15) * FRSB + (lane >> 4) * 16);

    float m_lo = -1e30f, m_hi = -1e30f, l_lo = 0.f, l_hi = 0.f;
    float o_acc[16][4];
#pragma unroll
    for (int nf = 0; nf < 16; nf++)
#pragma unroll
        for (int e = 0; e < 4; e++) o_acc[nf][e] = 0.f;

    const int row_lo_g = q0 + w * 16 + (lane >> 2);
    const int row_hi_g = row_lo_g + 8;

    for (int t = 0; t < nt; t++) {
        asm volatile("cp.async.wait_group 0;" ::: "memory");
        __syncthreads();
        if (t + 1 < nt) issue_kv(t + 1);

        const uint32_t stage = sb + 2 * FQ_BYTES + (t & 1) * FSTAGE;
        const uint32_t kb = stage + kvoff;
        const uint32_t kbl = kb + FKV_TILE;
        const uint32_t vb = stage + 2 * FKV_TILE + kvoff;
        const uint32_t vbl = vb + FKV_TILE;
        const int k0 = t << 6;

        float sa32[8][4];
        uint32_t sa16[8][2];
#pragma unroll
        for (int nf = 0; nf < 8; nf++) {
#pragma unroll
            for (int e = 0; e < 4; e++) sa32[nf][e] = 0.f;
            sa16[nf][0] = 0u;
            sa16[nf][1] = 0u;
        }

#pragma unroll
        for (int ks = 0; ks < 8; ks++) {
            uint32_t ah[4], al[4];
            LDSM4(ah[0], ah[1], ah[2], ah[3], qa_h + ks * 32);
            LDSM4(al[0], al[1], al[2], al[3], qa_l + ks * 32);
#pragma unroll
            for (int ng = 0; ng < 4; ng++) {
                uint32_t h0, h1, h2, h3, l0, l1, l2, l3;
                LDSM4(h0, h1, h2, h3, kb + ng * (16 * FRSB) + ks * 32);
                LDSM4(l0, l1, l2, l3, kbl + ng * (16 * FRSB) + ks * 32);
                uint32_t bh0[2] = {h0, h2}, bh1[2] = {h1, h3};
                uint32_t bl0[2] = {l0, l2}, bl1[2] = {l1, l3};
                MMA16816(sa32[2 * ng], ah, bh0);
                MMA16816H(sa16[2 * ng], al, bh0);
                MMA16816H(sa16[2 * ng], ah, bl0);
                MMA16816(sa32[2 * ng + 1], ah, bh1);
                MMA16816H(sa16[2 * ng + 1], al, bh1);
                MMA16816H(sa16[2 * ng + 1], ah, bl1);
            }
        }

        float sa[8][4];
#pragma unroll
        for (int nf = 0; nf < 8; nf++) {
            float2 rlo = h2f2(sa16[nf][0]);
            float2 rhi = h2f2(sa16[nf][1]);
            sa[nf][0] = sa32[nf][0] + rlo.x;
            sa[nf][1] = sa32[nf][1] + rlo.y;
            sa[nf][2] = sa32[nf][2] + rhi.x;
            sa[nf][3] = sa32[nf][3] + rhi.y;
        }

        if (t >= nt - 2) {
#pragma unroll
            for (int nf = 0; nf < 8; nf++) {
                int cb = k0 + nf * 8 + (lane & 3) * 2;
                if (cb > row_lo_g) sa[nf][0] = -1e30f;
                if (cb + 1 > row_lo_g) sa[nf][1] = -1e30f;
                if (cb > row_hi_g) sa[nf][2] = -1e30f;
                if (cb + 1 > row_hi_g) sa[nf][3] = -1e30f;
            }
        }

        float tm_lo = -1e30f, tm_hi = -1e30f;
#pragma unroll
        for (int nf = 0; nf < 8; nf++) {
            tm_lo = fmaxf(tm_lo, fmaxf(sa[nf][0], sa[nf][1]));
            tm_hi = fmaxf(tm_hi, fmaxf(sa[nf][2], sa[nf][3]));
        }
        tm_lo = fmaxf(tm_lo, __shfl_xor_sync(0xffffffffu, tm_lo, 1));
        tm_lo = fmaxf(tm_lo, __shfl_xor_sync(0xffffffffu, tm_lo, 2));
        tm_hi = fmaxf(tm_hi, __shfl_xor_sync(0xffffffffu, tm_hi, 1));
        tm_hi = fmaxf(tm_hi, __shfl_xor_sync(0xffffffffu, tm_hi, 2));

        float mn_lo = fmaxf(m_lo, tm_lo), mn_hi = fmaxf(m_hi, tm_hi);
        float al_lo = __expf(m_lo - mn_lo), al_hi = __expf(m_hi - mn_hi);
        m_lo = mn_lo; m_hi = mn_hi;

        float sum_lo = 0.f, sum_hi = 0.f;
#pragma unroll
        for (int nf = 0; nf < 8; nf++) {
            sa[nf][0] = __expf(sa[nf][0] - mn_lo);
            sa[nf][1] = __expf(sa[nf][1] - mn_lo);
            sa[nf][2] = __expf(sa[nf][2] - mn_hi);
            sa[nf][3] = __expf(sa[nf][3] - mn_hi);
            sum_lo += sa[nf][0] + sa[nf][1];
            sum_hi += sa[nf][2] + sa[nf][3];
        }
        sum_lo += __shfl_xor_sync(0xffffffffu, sum_lo, 1);
        sum_lo += __shfl_xor_sync(0xffffffffu, sum_lo, 2);
        sum_hi += __shfl_xor_sync(0xffffffffu, sum_hi, 1);
        sum_hi += __shfl_xor_sync(0xffffffffu, sum_hi, 2);
        l_lo = l_lo * al_lo + sum_lo;
        l_hi = l_hi * al_hi + sum_hi;

#pragma unroll
        for (int nf = 0; nf < 16; nf++) {
            o_acc[nf][0] *= al_lo; o_acc[nf][1] *= al_lo;
            o_acc[nf][2] *= al_hi; o_acc[nf][3] *= al_hi;
        }

        uint32_t pah[4][4], pal[4][4];
#pragma unroll
        for (int j = 0; j < 4; j++) {
            pah[j][0] = pack_h2f(sa[2 * j][0], sa[2 * j][1]);
            pal[j][0] = pack_resid(pah[j][0], sa[2 * j][0], sa[2 * j][1]);
            pah[j][1] = pack_h2f(sa[2 * j][2], sa[2 * j][3]);
            pal[j][1] = pack_resid(pah[j][1], sa[2 * j][2], sa[2 * j][3]);
            pah[j][2] = pack_h2f(sa[2 * j + 1][0], sa[2 * j + 1][1]);
            pal[j][2] = pack_resid(pah[j][2], sa[2 * j + 1][0], sa[2 * j + 1][1]);
            pah[j][3] = pack_h2f(sa[2 * j + 1][2], sa[2 * j + 1][3]);
            pal[j][3] = pack_resid(pah[j][3], sa[2 * j + 1][2], sa[2 * j + 1][3]);
        }

        uint32_t o16[16][2];
#pragma unroll
        for (int nf = 0; nf < 16; nf++) { o16[nf][0] = 0u; o16[nf][1] = 0u; }

#pragma unroll
        for (int j = 0; j < 4; j++) {
#pragma unroll
            for (int dg = 0; dg < 8; dg++) {
                uint32_t h0, h1, h2, h3, l0, l1, l2, l3;
                LDSM4T(h0, h1, h2, h3, vb + j * (16 * FRSB) + dg * 32);
                LDSM4T(l0, l1, l2, l3, vbl + j * (16 * FRSB) + dg * 32);
                uint32_t bh0[2] = {h0, h1}, bh1[2] = {h2, h3};
                uint32_t bl0[2] = {l0, l1}, bl1[2] = {l2, l3};
                MMA16816(o_acc[2 * dg], pah[j], bh0);
                MMA16816H(o16[2 * dg], pal[j], bh0);
                MMA16816H(o16[2 * dg], pah[j], bl0);
                MMA16816(o_acc[2 * dg + 1], pah[j], bh1);
                MMA16816H(o16[2 * dg + 1], pal[j], bh1);
                MMA16816H(o16[2 * dg + 1], pah[j], bl1);
            }
        }
#pragma unroll
        for (int nf = 0; nf < 16; nf++) {
            float2 rlo = h2f2(o16[nf][0]);
            float2 rhi = h2f2(o16[nf][1]);
            o_acc[nf][0] += rlo.x;
            o_acc[nf][1] += rlo.y;
            o_acc[nf][2] += rhi.x;
            o_acc[nf][3] += rhi.y;
        }
    }

    const float inv_lo = 1.f / l_lo, inv_hi = 1.f / l_hi;
#pragma unroll
    for (int nf = 0; nf < 16; nf++) {
        int col = head * HEAD_DIM + nf * 8 + (lane & 3) * 2;
        float o0 = o_acc[nf][0] * inv_lo, o1 = o_acc[nf][1] * inv_lo;
        float o2 = o_acc[nf][2] * inv_hi, o3 = o_acc[nf][3] * inv_hi;
        uint32_t h0 = pack_h2f(o0, o1), L0 = pack_resid(h0, o0, o1);
        uint32_t h1 = pack_h2f(o2, o3), L1 = pack_resid(h1, o2, o3);
        *(uint32_t*)(Oh + (size_t)row_lo_g * D_MODEL + col) = h0;
        *(uint32_t*)(Ol + (size_t)row_lo_g * D_MODEL + col) = L0;
        *(uint32_t*)(Oh + (size_t)row_hi_g * D_MODEL + col) = h1;
        *(uint32_t*)(Ol + (size_t)row_hi_g * D_MODEL + col) = L1;
    }
}

// ---------------------------------------------------------------------------
// Launch
// ---------------------------------------------------------------------------
extern "C" void kernel_launch(void* const* d_in, const int* in_sizes, int n_in,
                              void* d_out, int out_size) {
    const float* x  = (const float*)d_in[0];
    const float* fc = (const float*)d_in[1];
    const float* fs = (const float*)d_in[2];
    const float* wq = (const float*)d_in[4];
    const float* wk = (const float*)d_in[5];
    const float* wv = (const float*)d_in[6];
    const float* wo = (const float*)d_in[7];
    float* out = (float*)d_out;

    __half *xh, *xl, *qh, *ql, *kh, *kl, *vh, *vl, *aoh, *aol;
    __half *wqh, *wql, *wkh, *wkl, *wvh, *wvl, *woh, *wol;
    cudaGetSymbolAddress((void**)&xh,  g_xh);
    cudaGetSymbolAddress((void**)&xl,  g_xl);
    cudaGetSymbolAddress((void**)&qh,  g_qh);
    cudaGetSymbolAddress((void**)&ql,  g_ql);
    cudaGetSymbolAddress((void**)&kh,  g_kh);
    cudaGetSymbolAddress((void**)&kl,  g_kl);
    cudaGetSymbolAddress((void**)&vh,  g_vh);
    cudaGetSymbolAddress((void**)&vl,  g_vl);
    cudaGetSymbolAddress((void**)&aoh, g_aoh);
    cudaGetSymbolAddress((void**)&aol, g_aol);
    cudaGetSymbolAddress((void**)&wqh, g_wqh);
    cudaGetSymbolAddress((void**)&wql, g_wql);
    cudaGetSymbolAddress((void**)&wkh, g_wkh);
    cudaGetSymbolAddress((void**)&wkl, g_wkl);
    cudaGetSymbolAddress((void**)&wvh, g_wvh);
    cudaGetSymbolAddress((void**)&wvl, g_wvl);
    cudaGetSymbolAddress((void**)&woh, g_woh);
    cudaGetSymbolAddress((void**)&wol, g_wol);

    cudaFuncSetAttribute(qkv_gemm, cudaFuncAttributeMaxDynamicSharedMemorySize, G_SMEM);
    cudaFuncSetAttribute(wo_gemm,  cudaFuncAttributeMaxDynamicSharedMemorySize, G_SMEM);
    cudaFuncSetAttribute(flash_hmma, cudaFuncAttributeMaxDynamicSharedMemorySize, FSMEM);

    split_kernel<<<(S_LEN * D_MODEL + 255) / 256, 256>>>(x, xh, xl, S_LEN * D_MODEL);
    transpose_split_all<<<dim3(D_MODEL / 32, D_MODEL / 32, 4), dim3(32, 8)>>>(
        wq, wk, wv, wo, wqh, wql, wkh, wkl, wvh, wvl, woh, wol);

    qkv_gemm<<<dim3(48, S_LEN / 128), 512, G_SMEM>>>(
        xh, xl, fc, fs, wqh, wql, wkh, wkl, wvh, wvl,
        qh, ql, kh, kl, vh, vl);

    flash_hmma<<<dim3(S_LEN / 128, N_HEADS), 256, FSMEM>>>(
        qh, ql, kh, kl, vh, vl, aoh, aol);

    wo_gemm<<<dim3(D_MODEL / 128, S_LEN / 128), 512, G_SMEM>>>(
        aoh, aol, woh, wol, out);
}